// round 14
// baseline (speedup 1.0000x reference)
#include <cuda_runtime.h>
#include <cuda_bf16.h>
#include <cstdint>
#include <cstddef>

#define Bc 4
#define Nc 2048
#define Ec 32768
#define Dc 128
#define Lc 3
#define NRELc 1000
#define BEc (Bc*Ec)          // 131072 edges

// ---------------- static device scratch ----------------
__device__ float    g_h[Bc*Nc*Dc];
__device__ float    g_aggr[Bc*Nc*Dc];
__device__ float    g_sm[Bc*Nc];
__device__ float    g_raw[(size_t)BEc*Dc];    // 64 MB fp32
__device__ float    g_att[BEc];               // holds exp(att) now
__device__ float    g_gd[BEc];
__device__ float    g_relMsg[Lc*NRELc*Dc];    // h_r@W4 + msg_b
__device__ float    g_relDen[NRELc*Dc];
__device__ float    g_relBeta[NRELc];
__device__ float    g_relAtt[Lc*NRELc];
__device__ float    g_rqDen[Bc*Dc];
__device__ float    g_rqBeta[Bc];
__device__ float    g_rqAtt[Lc*Bc];
__device__ float    g_z0add[Lc*Dc];           // colsum(W3[k]) + (k==0)*colsum(W2[0])
__device__ float    g_hW2[Bc*Nc*Dc];          // h @ W2[k]   (layers 1,2)
__device__ uint4    g_Wfrag[7*4096];          // fragment-packed bf16 hi/lo weights
__device__ int      g_mflag = 0;              // zero-init; only OR'd with 1 (deterministic)

// ---------------- helpers ----------------
__device__ __forceinline__ float sgm(float x) { return 1.0f / (1.0f + __expf(-x)); }
__device__ __forceinline__ int ldmask(const void* p, int i) {
    return g_mflag ? (int)((const unsigned char*)p)[i] : ((const int*)p)[i];
}
__device__ __forceinline__ unsigned long long packdup(float a) {
    unsigned long long r; unsigned u = __float_as_uint(a);
    asm("mov.b64 %0, {%1, %1};" : "=l"(r) : "r"(u));
    return r;
}
__device__ __forceinline__ float2 unpk(unsigned long long v) {
    float2 f;
    asm("mov.b64 {%0, %1}, %2;" : "=f"(f.x), "=f"(f.y) : "l"(v));
    return f;
}
#define FMA2(acc, a, b) asm("fma.rn.f32x2 %0, %1, %2, %0;" : "+l"(acc) : "l"(a), "l"(b))
__device__ __forceinline__ void red_v4(float* p, float4 v) {
    asm volatile("red.global.add.v4.f32 [%0], {%1,%2,%3,%4};"
                 :: "l"(p), "f"(v.x), "f"(v.y), "f"(v.z), "f"(v.w) : "memory");
}
__device__ __forceinline__ void bsplit(float v, unsigned short& h, unsigned short& l) {
    __nv_bfloat16 hb = __float2bfloat16(v);
    h = __bfloat16_as_ushort(hb);
    l = __bfloat16_as_ushort(__float2bfloat16(v - __bfloat162float(hb)));
}
__device__ __forceinline__ void mma_bf16(float& d0, float& d1, float& d2, float& d3,
                                         uint32_t a0, uint32_t a1, uint32_t a2, uint32_t a3,
                                         uint32_t b0, uint32_t b1) {
    asm volatile(
        "mma.sync.aligned.m16n8k16.row.col.f32.bf16.bf16.f32 "
        "{%0,%1,%2,%3}, {%4,%5,%6,%7}, {%8,%9}, {%0,%1,%2,%3};"
        : "+f"(d0), "+f"(d1), "+f"(d2), "+f"(d3)
        : "r"(a0), "r"(a1), "r"(a2), "r"(a3), "r"(b0), "r"(b1));
}

#define INSTRIDE 132
#define SMEM_UPD ((128*INSTRIDE + 64*INSTRIDE)*4)
#define ASTRIDE 136
#define TILE 256                                   // edges per MMA block
#define SMEM_MMA (TILE*ASTRIDE*2*2 + 4096*16)      // 204800 B

// ---------------- upfront init (layer 0 state + mask detect) ----------------
__global__ void init_all_kernel(const unsigned* __restrict__ emk32) {
    int idx = blockIdx.x * 256 + threadIdx.x;
    g_aggr[idx] = 0.0f;
    int n = (idx >> 7) & (Nc - 1);
    g_h[idx] = (n == 0) ? 1.0f : 0.0f;
    if (idx < Bc * Nc) g_sm[idx] = 0.0f;
    if (idx < BEc / 4) {                      // 32768 words = BEc bytes
        if (emk32[idx] & 0xFFFFFF00u) atomicOr(&g_mflag, 1);
    }
}

// ---------------- prep combo: weight fragments (blk<112) + batch vectors (blk>=112) ----------------
// wfrag tiles: 0..2 = W1[k], 3..5 = W5[k], 6 = A3 (den_W1 rows 256..383)
__global__ void prep_combo_kernel(const float* __restrict__ msg_W,
                                  const float* __restrict__ den_W1,
                                  const float* __restrict__ rq,
                                  const float* __restrict__ den_b1,
                                  const float* __restrict__ beta_W,
                                  const float* __restrict__ beta_b,
                                  const float* __restrict__ att_W,
                                  const float* __restrict__ att_b) {
    if (blockIdx.x < 112) {
        int idx = blockIdx.x * 256 + threadIdx.x;   // 7*4096
        int tile = idx >> 12;
        int r = idx & 4095;
        int ks = r >> 9;
        int nt = (r >> 5) & 15;
        int lane = r & 31;
        int g = lane >> 2, tg = lane & 3;
        int n = nt * 8 + g;
        int k0 = ks * 16 + tg * 2;
        const float* base;
        if (tile < 3)      base = msg_W + ((size_t)tile * 640) * Dc;
        else if (tile < 6) base = msg_W + ((size_t)(tile - 3) * 640 + 512) * Dc;
        else               base = den_W1 + (size_t)256 * Dc;
        float v0 = base[(size_t)k0 * Dc + n],       v1 = base[(size_t)(k0 + 1) * Dc + n];
        float v8 = base[(size_t)(k0 + 8) * Dc + n], v9 = base[(size_t)(k0 + 9) * Dc + n];
        unsigned short h0, h1, h8, h9, l0, l1, l8, l9;
        bsplit(v0, h0, l0); bsplit(v1, h1, l1); bsplit(v8, h8, l8); bsplit(v9, h9, l9);
        g_Wfrag[idx] = make_uint4((uint32_t)h0 | ((uint32_t)h1 << 16),
                                  (uint32_t)h8 | ((uint32_t)h9 << 16),
                                  (uint32_t)l0 | ((uint32_t)l1 << 16),
                                  (uint32_t)l8 | ((uint32_t)l9 << 16));
        return;
    }
    int blk = blockIdx.x - 112;                 // 0..7
    int j = threadIdx.x;
    if (j >= 128) return;
    if (blk < 4) {
        int b = blk;
        float acc = 0;
        for (int i = 0; i < Dc; i++) acc += rq[b * Dc + i] * den_W1[(Dc + i) * Dc + j];
        g_rqDen[b * Dc + j] = acc + den_b1[j];
    } else if (blk < 7) {
        int k = blk - 4;
        float s = 0;
        for (int i = 0; i < Dc; i++) s += msg_W[(k * 640 + 256 + i) * Dc + j];
        if (k == 0)
            for (int i = 0; i < Dc; i++) s += msg_W[(0 * 640 + 128 + i) * Dc + j];
        g_z0add[k * Dc + j] = s;
    } else {
        if (j < Bc) {
            float s = 0;
            for (int i = 0; i < Dc; i++) s += rq[j * Dc + i] * beta_W[i];
            g_rqBeta[j] = s + beta_b[0];
        }
        if (j < Lc * Bc) {
            int k = j / Bc, b = j % Bc;
            float s = 0;
            for (int i = 0; i < Dc; i++) s += rq[b * Dc + i] * att_W[k * 384 + 256 + i];
            g_rqAtt[k * Bc + b] = s + att_b[k];
        }
    }
}

// ---------------- P0: per-relation tables (4-way K split, 512 threads) ----------------
__global__ void __launch_bounds__(512, 1)
rel_tables_kernel(const float* __restrict__ rel_table,
                  const float* __restrict__ den_W1,
                  const float* __restrict__ msg_W,
                  const float* __restrict__ msg_b,
                  const float* __restrict__ beta_W,
                  const float* __restrict__ att_W) {
    __shared__ float hr[4][Dc];
    __shared__ float part[4][4][4][Dc];   // [kquart][rel][mat][col] = 32 KB
    int tid = threadIdx.x;
    int col = tid & 127, kq = tid >> 7;   // kq in 0..3
    int r0 = blockIdx.x * 4;              // 250 blocks * 4 = 1000
    hr[tid >> 7][tid & 127] = rel_table[(size_t)(r0 + (tid >> 7)) * Dc + (tid & 127)];
    __syncthreads();
    float aD[4] = {0}, a0[4] = {0}, a1[4] = {0}, a2[4] = {0};
    int i0 = kq * 32;
    #pragma unroll 4
    for (int ii = 0; ii < 32; ii++) {
        int i = i0 + ii;
        float wD = den_W1[i * Dc + col];
        float w0 = msg_W[(0 * 640 + 384 + i) * Dc + col];
        float w1 = msg_W[(1 * 640 + 384 + i) * Dc + col];
        float w2 = msg_W[(2 * 640 + 384 + i) * Dc + col];
        #pragma unroll
        for (int u = 0; u < 4; u++) {
            float h = hr[u][i];
            aD[u] += h * wD; a0[u] += h * w0; a1[u] += h * w1; a2[u] += h * w2;
        }
    }
    #pragma unroll
    for (int u = 0; u < 4; u++) {
        part[kq][u][0][col] = aD[u];
        part[kq][u][1][col] = a0[u];
        part[kq][u][2][col] = a1[u];
        part[kq][u][3][col] = a2[u];
    }
    __syncthreads();
    {
        int u = kq;
        int r = r0 + u;
        float sD = part[0][u][0][col] + part[1][u][0][col] + part[2][u][0][col] + part[3][u][0][col];
        float s0 = part[0][u][1][col] + part[1][u][1][col] + part[2][u][1][col] + part[3][u][1][col];
        float s1 = part[0][u][2][col] + part[1][u][2][col] + part[2][u][2][col] + part[3][u][2][col];
        float s2 = part[0][u][3][col] + part[1][u][3][col] + part[2][u][3][col] + part[3][u][3][col];
        g_relDen[r * Dc + col] = sD;
        g_relMsg[(0 * NRELc + r) * Dc + col] = s0 + msg_b[col];
        g_relMsg[(1 * NRELc + r) * Dc + col] = s1 + msg_b[Dc + col];
        g_relMsg[(2 * NRELc + r) * Dc + col] = s2 + msg_b[2 * Dc + col];
    }
    if (tid < 4) {
        float s = 0;
        for (int i = 0; i < Dc; i++) s += hr[tid][i] * beta_W[i];
        g_relBeta[r0 + tid] = s;
    } else if (tid < 16) {
        int t = tid - 4; int u = t / 3, k = t % 3;
        float s = 0;
        for (int i = 0; i < Dc; i++) s += hr[u][i] * att_W[k * 384 + 128 + i];
        g_relAtt[k * NRELc + (r0 + u)] = s;
    }
}

// ---------------- msg MMA: phase1 (h.h_r)@W1 + phase2 conf@W5 (+ phase3 den/gate at k=0) ----------------
// Epilogue stores exp(att) and accumulates the softmax denominator directly
// (no max-pass: logits are O(10), exp is fp32-safe; masked edges contribute 0).
__global__ void __launch_bounds__(512, 1)
msg_mma_kernel(int k, const int* __restrict__ edge_index, const int* __restrict__ rels_g,
               const void* __restrict__ emk, const float* __restrict__ rel_table,
               const float* __restrict__ conf, const float* __restrict__ att_W,
               const float* __restrict__ scores, const void* __restrict__ ecm,
               const float* __restrict__ den_W2, const float* __restrict__ den_b2) {
    extern __shared__ char sm[];
    __nv_bfloat16* Ah = (__nv_bfloat16*)sm;
    __nv_bfloat16* Al = Ah + TILE * ASTRIDE;
    uint4* Bsm = (uint4*)(Al + TILE * ASTRIDE);
    __shared__ int s_src[TILE];
    __shared__ int s_rel[TILE];
    __shared__ float s_aw[128];
    int tid = threadIdx.x, w = tid >> 5, lane = tid & 31;
    int g = lane >> 2, tg = lane & 3;
    int e0 = blockIdx.x * TILE, b = e0 >> 15;
    int ebi0 = e0 & (Ec - 1);
    if (tid < TILE) {
        s_src[tid] = edge_index[(size_t)b * 2 * Ec + ebi0 + tid];
        s_rel[tid] = rels_g[e0 + tid];
    }
    if (tid < 128) s_aw[tid] = att_W[(size_t)k * 384 + tid];
    for (int i = tid; i < 4096; i += 512) Bsm[i] = g_Wfrag[k * 4096 + i];
    __syncthreads();

    // ---- phase 1: A = h_src * h_r ----
    #pragma unroll
    for (int it = 0; it < 16; it++) {
        int idx = it * 512 + tid;
        int row = idx >> 5, c4 = (idx & 31) * 4;
        float4 hv = *(const float4*)&g_h[((size_t)(b * Nc + s_src[row])) * Dc + c4];
        float4 rv = *(const float4*)&rel_table[(size_t)s_rel[row] * Dc + c4];
        float4 v = make_float4(hv.x * rv.x, hv.y * rv.y, hv.z * rv.z, hv.w * rv.w);
        unsigned short h[4], l[4];
        bsplit(v.x, h[0], l[0]); bsplit(v.y, h[1], l[1]);
        bsplit(v.z, h[2], l[2]); bsplit(v.w, h[3], l[3]);
        *(uint2*)&Ah[row * ASTRIDE + c4] = make_uint2((uint32_t)h[0] | ((uint32_t)h[1] << 16),
                                                      (uint32_t)h[2] | ((uint32_t)h[3] << 16));
        *(uint2*)&Al[row * ASTRIDE + c4] = make_uint2((uint32_t)l[0] | ((uint32_t)l[1] << 16),
                                                      (uint32_t)l[2] | ((uint32_t)l[3] << 16));
    }
    __syncthreads();

    int R = w * 16;
    float d[16][4];
    #pragma unroll
    for (int t = 0; t < 16; t++) { d[t][0] = d[t][1] = d[t][2] = d[t][3] = 0.0f; }
    #pragma unroll
    for (int ks = 0; ks < 8; ks++) {
        int ko = ks * 16 + tg * 2;
        uint32_t ah0 = *(uint32_t*)&Ah[(R + g) * ASTRIDE + ko];
        uint32_t ah1 = *(uint32_t*)&Ah[(R + g + 8) * ASTRIDE + ko];
        uint32_t ah2 = *(uint32_t*)&Ah[(R + g) * ASTRIDE + ko + 8];
        uint32_t ah3 = *(uint32_t*)&Ah[(R + g + 8) * ASTRIDE + ko + 8];
        uint32_t al0 = *(uint32_t*)&Al[(R + g) * ASTRIDE + ko];
        uint32_t al1 = *(uint32_t*)&Al[(R + g + 8) * ASTRIDE + ko];
        uint32_t al2 = *(uint32_t*)&Al[(R + g) * ASTRIDE + ko + 8];
        uint32_t al3 = *(uint32_t*)&Al[(R + g + 8) * ASTRIDE + ko + 8];
        #pragma unroll
        for (int nt = 0; nt < 16; nt++) {
            uint4 bf = Bsm[(ks * 16 + nt) * 32 + lane];
            mma_bf16(d[nt][0], d[nt][1], d[nt][2], d[nt][3], ah0, ah1, ah2, ah3, bf.x, bf.y);
            mma_bf16(d[nt][0], d[nt][1], d[nt][2], d[nt][3], ah0, ah1, ah2, ah3, bf.z, bf.w);
            mma_bf16(d[nt][0], d[nt][1], d[nt][2], d[nt][3], al0, al1, al2, al3, bf.x, bf.y);
        }
    }
    __syncthreads();    // all warps done reading A/B of phase 1

    // ---- phase 2: A = conf, B = W5[k] ----
    for (int i = tid; i < 4096; i += 512) Bsm[i] = g_Wfrag[(3 + k) * 4096 + i];
    #pragma unroll
    for (int it = 0; it < 16; it++) {
        int idx = it * 512 + tid;
        int row = idx >> 5, c4 = (idx & 31) * 4;
        float4 v = *(const float4*)&conf[((size_t)(e0 + row)) * Dc + c4];
        unsigned short h[4], l[4];
        bsplit(v.x, h[0], l[0]); bsplit(v.y, h[1], l[1]);
        bsplit(v.z, h[2], l[2]); bsplit(v.w, h[3], l[3]);
        *(uint2*)&Ah[row * ASTRIDE + c4] = make_uint2((uint32_t)h[0] | ((uint32_t)h[1] << 16),
                                                      (uint32_t)h[2] | ((uint32_t)h[3] << 16));
        *(uint2*)&Al[row * ASTRIDE + c4] = make_uint2((uint32_t)l[0] | ((uint32_t)l[1] << 16),
                                                      (uint32_t)l[2] | ((uint32_t)l[3] << 16));
    }
    __syncthreads();
    #pragma unroll
    for (int ks = 0; ks < 8; ks++) {
        int ko = ks * 16 + tg * 2;
        uint32_t ah0 = *(uint32_t*)&Ah[(R + g) * ASTRIDE + ko];
        uint32_t ah1 = *(uint32_t*)&Ah[(R + g + 8) * ASTRIDE + ko];
        uint32_t ah2 = *(uint32_t*)&Ah[(R + g) * ASTRIDE + ko + 8];
        uint32_t ah3 = *(uint32_t*)&Ah[(R + g + 8) * ASTRIDE + ko + 8];
        uint32_t al0 = *(uint32_t*)&Al[(R + g) * ASTRIDE + ko];
        uint32_t al1 = *(uint32_t*)&Al[(R + g + 8) * ASTRIDE + ko];
        uint32_t al2 = *(uint32_t*)&Al[(R + g) * ASTRIDE + ko + 8];
        uint32_t al3 = *(uint32_t*)&Al[(R + g + 8) * ASTRIDE + ko + 8];
        #pragma unroll
        for (int nt = 0; nt < 16; nt++) {
            uint4 bf = Bsm[(ks * 16 + nt) * 32 + lane];
            mma_bf16(d[nt][0], d[nt][1], d[nt][2], d[nt][3], ah0, ah1, ah2, ah3, bf.x, bf.y);
            mma_bf16(d[nt][0], d[nt][1], d[nt][2], d[nt][3], ah0, ah1, ah2, ah3, bf.z, bf.w);
            mma_bf16(d[nt][0], d[nt][1], d[nt][2], d[nt][3], al0, al1, al2, al3, bf.x, bf.y);
        }
    }

    // ---- epilogue: 2 rows per thread ----
    int r0 = R + g, r1 = R + g + 8;
    int ea = e0 + r0, eb = e0 + r1;
    int ra = s_rel[r0], rb = s_rel[r1];
    int sa = s_src[r0], sbn = s_src[r1];
    bool za = (sa == 0), zb = (sbn == 0);
    const float* rma = &g_relMsg[((size_t)k * NRELc + ra) * Dc];
    const float* rmb = &g_relMsg[((size_t)k * NRELc + rb) * Dc];
    const float* hwa = &g_hW2[((size_t)(b * Nc + sa)) * Dc];
    const float* hwb = &g_hW2[((size_t)(b * Nc + sbn)) * Dc];
    const float* z0t = &g_z0add[k * Dc];
    float pa = 0, pb = 0;
    #pragma unroll
    for (int nt = 0; nt < 16; nt++) {
        int col = nt * 8 + tg * 2;
        float2 ta = *(const float2*)&rma[col];
        float2 tb = *(const float2*)&rmb[col];
        float v0 = d[nt][0] + ta.x;
        float v1 = d[nt][1] + ta.y;
        float v2 = d[nt][2] + tb.x;
        float v3 = d[nt][3] + tb.y;
        if (k > 0) {
            float2 ha = *(const float2*)&hwa[col];
            float2 hb = *(const float2*)&hwb[col];
            v0 += ha.x; v1 += ha.y; v2 += hb.x; v3 += hb.y;
        }
        if (za || zb) {
            float2 zv = *(const float2*)&z0t[col];
            if (za) { v0 += zv.x; v1 += zv.y; }
            if (zb) { v2 += zv.x; v3 += zv.y; }
        }
        v0 = fmaxf(v0, 0.0f); v1 = fmaxf(v1, 0.0f);
        v2 = fmaxf(v2, 0.0f); v3 = fmaxf(v3, 0.0f);
        float aw0 = s_aw[col], aw1 = s_aw[col + 1];
        pa += v0 * aw0 + v1 * aw1;
        pb += v2 * aw0 + v3 * aw1;
        *(float2*)&g_raw[(size_t)ea * Dc + col] = make_float2(v0, v1);
        *(float2*)&g_raw[(size_t)eb * Dc + col] = make_float2(v2, v3);
    }
    pa += __shfl_xor_sync(0xffffffffu, pa, 1); pa += __shfl_xor_sync(0xffffffffu, pa, 2);
    pb += __shfl_xor_sync(0xffffffffu, pb, 1); pb += __shfl_xor_sync(0xffffffffu, pb, 2);
    if (tg == 0) {
        int es[2] = {ea, eb};
        int rr2[2] = {ra, rb};
        float ps[2] = {pa, pb};
        #pragma unroll
        for (int q = 0; q < 2; q++) {
            int e = es[q];
            float att = ps[q] + g_relAtt[k * NRELc + rr2[q]] + g_rqAtt[k * Bc + b];
            att = att > 0.0f ? att : 0.01f * att;
            float ex = ldmask(emk, e) ? __expf(att) : 0.0f;
            g_att[e] = ex;
            int tgt = edge_index[(size_t)(b * 2 + 1) * Ec + (e & (Ec - 1))];
            if (ex != 0.0f) atomicAdd(&g_sm[b * Nc + tgt], ex);
        }
    }

    // ---- phase 3 (k == 0 only): conf @ A3 -> den/gate (conf still staged in Ah/Al) ----
    if (k == 0) {
        __syncthreads();    // phase-2 B reads complete in all warps
        for (int i = tid; i < 4096; i += 512) Bsm[i] = g_Wfrag[6 * 4096 + i];
        __syncthreads();
        #pragma unroll
        for (int t = 0; t < 16; t++) { d[t][0] = d[t][1] = d[t][2] = d[t][3] = 0.0f; }
        #pragma unroll
        for (int ks = 0; ks < 8; ks++) {
            int ko = ks * 16 + tg * 2;
            uint32_t ah0 = *(uint32_t*)&Ah[(R + g) * ASTRIDE + ko];
            uint32_t ah1 = *(uint32_t*)&Ah[(R + g + 8) * ASTRIDE + ko];
            uint32_t ah2 = *(uint32_t*)&Ah[(R + g) * ASTRIDE + ko + 8];
            uint32_t ah3 = *(uint32_t*)&Ah[(R + g + 8) * ASTRIDE + ko + 8];
            uint32_t al0 = *(uint32_t*)&Al[(R + g) * ASTRIDE + ko];
            uint32_t al1 = *(uint32_t*)&Al[(R + g + 8) * ASTRIDE + ko];
            uint32_t al2 = *(uint32_t*)&Al[(R + g) * ASTRIDE + ko + 8];
            uint32_t al3 = *(uint32_t*)&Al[(R + g + 8) * ASTRIDE + ko + 8];
            #pragma unroll
            for (int nt = 0; nt < 16; nt++) {
                uint4 bf = Bsm[(ks * 16 + nt) * 32 + lane];
                mma_bf16(d[nt][0], d[nt][1], d[nt][2], d[nt][3], ah0, ah1, ah2, ah3, bf.x, bf.y);
                mma_bf16(d[nt][0], d[nt][1], d[nt][2], d[nt][3], ah0, ah1, ah2, ah3, bf.z, bf.w);
                mma_bf16(d[nt][0], d[nt][1], d[nt][2], d[nt][3], al0, al1, al2, al3, bf.x, bf.y);
            }
        }
        const float* qd = &g_rqDen[b * Dc];
        float sda = 0, sdb = 0;
        #pragma unroll
        for (int nt = 0; nt < 16; nt++) {
            int col = nt * 8 + tg * 2;
            float2 qv = *(const float2*)&qd[col];
            float2 da = *(const float2*)&g_relDen[ra * Dc + col];
            float2 db = *(const float2*)&g_relDen[rb * Dc + col];
            float2 w2 = *(const float2*)&den_W2[col];
            sda += fmaxf(d[nt][0] + da.x + qv.x, 0.0f) * w2.x
                 + fmaxf(d[nt][1] + da.y + qv.y, 0.0f) * w2.y;
            sdb += fmaxf(d[nt][2] + db.x + qv.x, 0.0f) * w2.x
                 + fmaxf(d[nt][3] + db.y + qv.y, 0.0f) * w2.y;
        }
        sda += __shfl_xor_sync(0xffffffffu, sda, 1); sda += __shfl_xor_sync(0xffffffffu, sda, 2);
        sdb += __shfl_xor_sync(0xffffffffu, sdb, 1); sdb += __shfl_xor_sync(0xffffffffu, sdb, 2);
        if (tg == 0) {
            float bv = den_b2[0];
            int es[2] = {ea, eb};
            float ss[2] = {sda, sdb};
            int rr2[2] = {ra, rb};
            #pragma unroll
            for (int q = 0; q < 2; q++) {
                int e = es[q], rel = rr2[q];
                float den = sgm(ss[q] + bv);
                den *= ldmask(emk, e) ? 1.0f : 0.0f;
                float beta = sgm(g_relBeta[rel] + g_rqBeta[b]);
                float gate = ldmask(ecm, e) ? sgm((scores[e] - beta) * 10.0f) : 0.5f;
                g_gd[e] = gate * den;
            }
        }
    }
}

// ---------------- K3: weighted message scatter ----------------
__global__ void scatter_kernel(const int* __restrict__ edge_index) {
    int gt = blockIdx.x * blockDim.x + threadIdx.x;
    int glob = gt >> 5;
    int l = threadIdx.x & 31;
    if (glob >= BEc) return;
    int b = glob >> 15, ebi = glob & (Ec - 1);
    float wv = 0.0f;
    int tgt = 0;
    if (l == 0) {
        tgt = edge_index[(size_t)(b * 2 + 1) * Ec + ebi];
        float gd = g_gd[glob];
        if (gd != 0.0f) {
            float ex = g_att[glob];
            if (ex != 0.0f) {
                float sden = g_sm[b * Nc + tgt];
                wv = gd * ex / (sden + 1e-8f);
            }
        }
    }
    wv  = __shfl_sync(0xffffffffu, wv, 0);
    tgt = __shfl_sync(0xffffffffu, tgt, 0);
    if (wv != 0.0f) {
        float4 rm = *(const float4*)&g_raw[((size_t)glob) * Dc + 4 * l];
        float4 v = make_float4(wv * rm.x, wv * rm.y, wv * rm.z, wv * rm.w);
        red_v4(&g_aggr[((size_t)(b * Nc + tgt)) * Dc + 4 * l], v);
    }
}

// ---------------- K4: update GEMM + LN (+ reset + fused hW2 for next layer) ----------------
__global__ void __launch_bounds__(256, 1)
upd_kernel(int k, int doNext, const float* __restrict__ upd_W, const float* __restrict__ upd_b,
           const float* __restrict__ ln_g, const float* __restrict__ ln_b,
           const float* __restrict__ msg_W, float* __restrict__ out) {
    extern __shared__ float smemf[];
    float* Ws = smemf;
    float* Ag = smemf + 128 * INSTRIDE;
    __shared__ float mus[64], rst[64];
    int tid = threadIdx.x;
    int w = tid >> 5, l = tid & 31;
    int n0 = blockIdx.x * 64;
    #pragma unroll
    for (int rr = 0; rr < 16; rr++) {
        int kk = w * 16 + rr;
        *(float4*)&Ws[kk * INSTRIDE + 4 * l] = *(const float4*)&upd_W[((size_t)k * Dc + kk) * Dc + 4 * l];
    }
    #pragma unroll
    for (int rr = 0; rr < 8; rr++) {
        int nl = w * 8 + rr;
        *(float4*)&Ag[nl * INSTRIDE + 4 * l] = *(const float4*)&g_aggr[((size_t)(n0 + nl)) * Dc + 4 * l];
    }
    __syncthreads();
    int ty = tid >> 4, tx = tid & 15;
    unsigned long long acc[4][4] = {};
    #pragma unroll 2
    for (int kk4 = 0; kk4 < Dc; kk4 += 4) {
        float avv[4][4];
        #pragma unroll
        for (int r = 0; r < 4; r++)
            *(float4*)avv[r] = *(const float4*)&Ag[(ty * 4 + r) * INSTRIDE + kk4];
        #pragma unroll
        for (int u = 0; u < 4; u++) {
            const ulonglong2* wp = (const ulonglong2*)&Ws[(kk4 + u) * INSTRIDE + tx * 8];
            ulonglong2 wa = wp[0], wb = wp[1];
            #pragma unroll
            for (int r = 0; r < 4; r++) {
                unsigned long long a2 = packdup(avv[r][u]);
                FMA2(acc[r][0], a2, wa.x); FMA2(acc[r][1], a2, wa.y);
                FMA2(acc[r][2], a2, wb.x); FMA2(acc[r][3], a2, wb.y);
            }
        }
    }
    __syncthreads();

    float vbuf[4][8];
    float s1[4] = {0}, s2[4] = {0};
    #pragma unroll
    for (int r = 0; r < 4; r++) {
        int n = n0 + ty * 4 + r;
        float vout[8];
        #pragma unroll
        for (int q = 0; q < 4; q++) { float2 u = unpk(acc[r][q]); vout[2*q] = u.x; vout[2*q+1] = u.y; }
        #pragma unroll
        for (int c = 0; c < 8; c++) {
            int j = tx * 8 + c;
            float v = g_h[((size_t)n) * Dc + j] + vout[c] + upd_b[k * Dc + j];
            vbuf[r][c] = v;
            s1[r] += v;
            s2[r] += v * v;
        }
    }
    float* red1 = Ag;
    float* red2 = Ag + 64 * 17;
    #pragma unroll
    for (int r = 0; r < 4; r++) {
        red1[(ty * 4 + r) * 17 + tx] = s1[r];
        red2[(ty * 4 + r) * 17 + tx] = s2[r];
    }
    __syncthreads();
    if (tid < 64) {
        float a = 0, bb = 0;
        #pragma unroll
        for (int t = 0; t < 16; t++) { a += red1[tid * 17 + t]; bb += red2[tid * 17 + t]; }
        float mu = a * (1.0f / Dc);
        float var = bb * (1.0f / Dc) - mu * mu;
        mus[tid] = mu;
        rst[tid] = rsqrtf(var + 1e-5f);
    }
    __syncthreads();
    #pragma unroll
    for (int r = 0; r < 4; r++) {
        int nl = ty * 4 + r;
        int n = n0 + nl;
        float mu = mus[nl], rs = rst[nl];
        float y[8];
        #pragma unroll
        for (int c = 0; c < 8; c++) {
            int j = tx * 8 + c;
            y[c] = (vbuf[r][c] - mu) * rs * ln_g[j] + ln_b[j];
        }
        *(float4*)&g_h[((size_t)n) * Dc + tx * 8]     = make_float4(y[0], y[1], y[2], y[3]);
        *(float4*)&g_h[((size_t)n) * Dc + tx * 8 + 4] = make_float4(y[4], y[5], y[6], y[7]);
        *(float4*)&Ag[nl * INSTRIDE + tx * 8]     = make_float4(y[0], y[1], y[2], y[3]);
        *(float4*)&Ag[nl * INSTRIDE + tx * 8 + 4] = make_float4(y[4], y[5], y[6], y[7]);
        if ((n & (Nc - 1)) == 0) {
            int b = n >> 11;
            #pragma unroll
            for (int c = 0; c < 8; c++) out[((size_t)b * Lc + k) * Dc + tx * 8 + c] = y[c];
        }
    }

    if (doNext) {
        float4 z = make_float4(0, 0, 0, 0);
        #pragma unroll
        for (int rr = 0; rr < 8; rr++) {
            int nl = w * 8 + rr;
            *(float4*)&g_aggr[((size_t)(n0 + nl)) * Dc + 4 * l] = z;
        }
        if (tid < 64) g_sm[n0 + tid] = 0.0f;
        __syncthreads();
        #pragma unroll
        for (int rr = 0; rr < 16; rr++) {
            int kk = w * 16 + rr;
            *(float4*)&Ws[kk * INSTRIDE + 4 * l] =
                *(const float4*)&msg_W[((size_t)(k + 1) * 640 + 128 + kk) * Dc + 4 * l];
        }
        __syncthreads();
        unsigned long long acc2[4][4] = {};
        #pragma unroll 2
        for (int kk4 = 0; kk4 < Dc; kk4 += 4) {
            float avv[4][4];
            #pragma unroll
            for (int r = 0; r < 4; r++)
                *(float4*)avv[r] = *(const float4*)&Ag[(ty * 4 + r) * INSTRIDE + kk4];
            #pragma unroll
            for (int u = 0; u < 4; u++) {
                const ulonglong2* wp = (const ulonglong2*)&Ws[(kk4 + u) * INSTRIDE + tx * 8];
                ulonglong2 wa = wp[0], wb = wp[1];
                #pragma unroll
                for (int r = 0; r < 4; r++) {
                    unsigned long long a2 = packdup(avv[r][u]);
                    FMA2(acc2[r][0], a2, wa.x); FMA2(acc2[r][1], a2, wa.y);
                    FMA2(acc2[r][2], a2, wb.x); FMA2(acc2[r][3], a2, wb.y);
                }
            }
        }
        #pragma unroll
        for (int r = 0; r < 4; r++) {
            int n = n0 + ty * 4 + r;
            float vout[8];
            #pragma unroll
            for (int q = 0; q < 4; q++) { float2 u = unpk(acc2[r][q]); vout[2*q] = u.x; vout[2*q+1] = u.y; }
            *(float4*)&g_hW2[((size_t)n) * Dc + tx * 8]     = make_float4(vout[0], vout[1], vout[2], vout[3]);
            *(float4*)&g_hW2[((size_t)n) * Dc + tx * 8 + 4] = make_float4(vout[4], vout[5], vout[6], vout[7]);
        }
    }
}

// ---------------- launch ----------------
extern "C" void kernel_launch(void* const* d_in, const int* in_sizes, int n_in,
                              void* d_out, int out_size) {
    const int*   edge_index = (const int*)d_in[0];
    const int*   rels       = (const int*)d_in[1];
    const float* scores     = (const float*)d_in[2];
    const void*  ecm        = d_in[3];
    const void*  emk        = d_in[4];
    // d_in[5] = mask (unused)
    const float* rq         = (const float*)d_in[6];
    const float* conf       = (const float*)d_in[7];
    const float* rel_table  = (const float*)d_in[8];
    const float* beta_W     = (const float*)d_in[9];
    const float* beta_b     = (const float*)d_in[10];
    const float* msg_W      = (const float*)d_in[11];
    const float* msg_b      = (const float*)d_in[12];
    const float* upd_W      = (const float*)d_in[13];
    const float* upd_b      = (const float*)d_in[14];
    const float* ln_g       = (const float*)d_in[15];
    const float* ln_b       = (const float*)d_in[16];
    const float* att_W      = (const float*)d_in[17];
    const float* att_b      = (const float*)d_in[18];
    const float* den_W1     = (const float*)d_in[19];
    const float* den_b1     = (const float*)d_in[20];
    const float* den_W2     = (const float*)d_in[21];
    const float* den_b2     = (const float*)d_in[22];
    float* out = (float*)d_out;

    cudaFuncSetAttribute(msg_mma_kernel, cudaFuncAttributeMaxDynamicSharedMemorySize, SMEM_MMA);
    cudaFuncSetAttribute(upd_kernel,     cudaFuncAttributeMaxDynamicSharedMemorySize, SMEM_UPD);

    init_all_kernel<<<(Bc * Nc * Dc) / 256, 256>>>((const unsigned*)emk);
    prep_combo_kernel<<<120, 256>>>(msg_W, den_W1, rq, den_b1, beta_W, beta_b, att_W, att_b);
    rel_tables_kernel<<<250, 512>>>(rel_table, den_W1, msg_W, msg_b, beta_W, att_W);

    for (int k = 0; k < Lc; k++) {
        msg_mma_kernel<<<BEc / TILE, 512, SMEM_MMA>>>(k, edge_index, rels, emk, rel_table,
                                                      conf, att_W, scores, ecm, den_W2, den_b2);
        scatter_kernel<<<(BEc * 32) / 256, 256>>>(edge_index);
        upd_kernel<<<(Bc * Nc) / 64, 256, SMEM_UPD>>>(k, (k < Lc - 1) ? 1 : 0,
                                                      upd_W, upd_b, ln_g, ln_b, msg_W, out);
    }
}

// round 15
// speedup vs baseline: 1.0364x; 1.0364x over previous
#include <cuda_runtime.h>
#include <cuda_bf16.h>
#include <cstdint>
#include <cstddef>

#define Bc 4
#define Nc 2048
#define Ec 32768
#define Dc 128
#define Lc 3
#define NRELc 1000
#define BEc (Bc*Ec)          // 131072 edges

// ---------------- static device scratch ----------------
__device__ float    g_h[Bc*Nc*Dc];
__device__ float    g_aggr[Bc*Nc*Dc];
__device__ float    g_sm[Bc*Nc];
__device__ float    g_raw[(size_t)BEc*Dc];    // 64 MB fp32
__device__ float    g_att[BEc];               // holds exp(att)
__device__ float    g_gd[BEc];
__device__ float    g_relMsg[Lc*NRELc*Dc];    // h_r@W4 + msg_b
__device__ float    g_relDen[NRELc*Dc];
__device__ float    g_relBeta[NRELc];
__device__ float    g_relAtt[Lc*NRELc];
__device__ float    g_rqDen[Bc*Dc];
__device__ float    g_rqBeta[Bc];
__device__ float    g_rqAtt[Lc*Bc];
__device__ float    g_z0add[Lc*Dc];           // colsum(W3[k]) + (k==0)*colsum(W2[0])
__device__ float    g_hW2[Bc*Nc*Dc];          // h @ W2[k]   (layers 1,2)
__device__ uint4    g_Wfrag[7*4096];          // fragment-packed bf16 hi/lo weights
__device__ int      g_mflag = 0;              // zero-init; only OR'd with 1 (deterministic)

// ---------------- helpers ----------------
__device__ __forceinline__ float sgm(float x) { return 1.0f / (1.0f + __expf(-x)); }
__device__ __forceinline__ int ldmask(const void* p, int i) {
    return g_mflag ? (int)((const unsigned char*)p)[i] : ((const int*)p)[i];
}
__device__ __forceinline__ unsigned long long packdup(float a) {
    unsigned long long r; unsigned u = __float_as_uint(a);
    asm("mov.b64 %0, {%1, %1};" : "=l"(r) : "r"(u));
    return r;
}
__device__ __forceinline__ float2 unpk(unsigned long long v) {
    float2 f;
    asm("mov.b64 {%0, %1}, %2;" : "=f"(f.x), "=f"(f.y) : "l"(v));
    return f;
}
#define FMA2(acc, a, b) asm("fma.rn.f32x2 %0, %1, %2, %0;" : "+l"(acc) : "l"(a), "l"(b))
__device__ __forceinline__ void red_v4(float* p, float4 v) {
    asm volatile("red.global.add.v4.f32 [%0], {%1,%2,%3,%4};"
                 :: "l"(p), "f"(v.x), "f"(v.y), "f"(v.z), "f"(v.w) : "memory");
}
__device__ __forceinline__ void bsplit(float v, unsigned short& h, unsigned short& l) {
    __nv_bfloat16 hb = __float2bfloat16(v);
    h = __bfloat16_as_ushort(hb);
    l = __bfloat16_as_ushort(__float2bfloat16(v - __bfloat162float(hb)));
}
__device__ __forceinline__ void mma_bf16(float& d0, float& d1, float& d2, float& d3,
                                         uint32_t a0, uint32_t a1, uint32_t a2, uint32_t a3,
                                         uint32_t b0, uint32_t b1) {
    asm volatile(
        "mma.sync.aligned.m16n8k16.row.col.f32.bf16.bf16.f32 "
        "{%0,%1,%2,%3}, {%4,%5,%6,%7}, {%8,%9}, {%0,%1,%2,%3};"
        : "+f"(d0), "+f"(d1), "+f"(d2), "+f"(d3)
        : "r"(a0), "r"(a1), "r"(a2), "r"(a3), "r"(b0), "r"(b1));
}

#define INSTRIDE 132
#define SMEM_UPD ((128*INSTRIDE + 64*INSTRIDE)*4)
#define ASTRIDE 136
#define TILE 256                                   // edges per MMA block
#define SMEM_MMA (TILE*ASTRIDE*2*2 + 4096*16)      // 204800 B

// ---------------- upfront init (layer 0 state + mask detect) ----------------
__global__ void init_all_kernel(const unsigned* __restrict__ emk32) {
    int idx = blockIdx.x * 256 + threadIdx.x;
    g_aggr[idx] = 0.0f;
    int n = (idx >> 7) & (Nc - 1);
    g_h[idx] = (n == 0) ? 1.0f : 0.0f;
    if (idx < Bc * Nc) g_sm[idx] = 0.0f;
    if (idx < BEc / 4) {                      // 32768 words = BEc bytes
        if (emk32[idx] & 0xFFFFFF00u) atomicOr(&g_mflag, 1);
    }
}

// ---------------- prep combo: weight fragments (blk<112) + batch vectors (blk>=112) ----------------
// wfrag tiles: 0..2 = W1[k], 3..5 = W5[k], 6 = A3 (den_W1 rows 256..383)
__global__ void prep_combo_kernel(const float* __restrict__ msg_W,
                                  const float* __restrict__ den_W1,
                                  const float* __restrict__ rq,
                                  const float* __restrict__ den_b1,
                                  const float* __restrict__ beta_W,
                                  const float* __restrict__ beta_b,
                                  const float* __restrict__ att_W,
                                  const float* __restrict__ att_b) {
    if (blockIdx.x < 112) {
        int idx = blockIdx.x * 256 + threadIdx.x;   // 7*4096
        int tile = idx >> 12;
        int r = idx & 4095;
        int ks = r >> 9;
        int nt = (r >> 5) & 15;
        int lane = r & 31;
        int g = lane >> 2, tg = lane & 3;
        int n = nt * 8 + g;
        int k0 = ks * 16 + tg * 2;
        const float* base;
        if (tile < 3)      base = msg_W + ((size_t)tile * 640) * Dc;
        else if (tile < 6) base = msg_W + ((size_t)(tile - 3) * 640 + 512) * Dc;
        else               base = den_W1 + (size_t)256 * Dc;
        float v0 = base[(size_t)k0 * Dc + n],       v1 = base[(size_t)(k0 + 1) * Dc + n];
        float v8 = base[(size_t)(k0 + 8) * Dc + n], v9 = base[(size_t)(k0 + 9) * Dc + n];
        unsigned short h0, h1, h8, h9, l0, l1, l8, l9;
        bsplit(v0, h0, l0); bsplit(v1, h1, l1); bsplit(v8, h8, l8); bsplit(v9, h9, l9);
        g_Wfrag[idx] = make_uint4((uint32_t)h0 | ((uint32_t)h1 << 16),
                                  (uint32_t)h8 | ((uint32_t)h9 << 16),
                                  (uint32_t)l0 | ((uint32_t)l1 << 16),
                                  (uint32_t)l8 | ((uint32_t)l9 << 16));
        return;
    }
    int blk = blockIdx.x - 112;                 // 0..7
    int j = threadIdx.x;
    if (j >= 128) return;
    if (blk < 4) {
        int b = blk;
        float acc = 0;
        for (int i = 0; i < Dc; i++) acc += rq[b * Dc + i] * den_W1[(Dc + i) * Dc + j];
        g_rqDen[b * Dc + j] = acc + den_b1[j];
    } else if (blk < 7) {
        int k = blk - 4;
        float s = 0;
        for (int i = 0; i < Dc; i++) s += msg_W[(k * 640 + 256 + i) * Dc + j];
        if (k == 0)
            for (int i = 0; i < Dc; i++) s += msg_W[(0 * 640 + 128 + i) * Dc + j];
        g_z0add[k * Dc + j] = s;
    } else {
        if (j < Bc) {
            float s = 0;
            for (int i = 0; i < Dc; i++) s += rq[j * Dc + i] * beta_W[i];
            g_rqBeta[j] = s + beta_b[0];
        }
        if (j < Lc * Bc) {
            int k = j / Bc, b = j % Bc;
            float s = 0;
            for (int i = 0; i < Dc; i++) s += rq[b * Dc + i] * att_W[k * 384 + 256 + i];
            g_rqAtt[k * Bc + b] = s + att_b[k];
        }
    }
}

// ---------------- P0: per-relation tables (4-way K split, 512 threads) ----------------
__global__ void __launch_bounds__(512, 1)
rel_tables_kernel(const float* __restrict__ rel_table,
                  const float* __restrict__ den_W1,
                  const float* __restrict__ msg_W,
                  const float* __restrict__ msg_b,
                  const float* __restrict__ beta_W,
                  const float* __restrict__ att_W) {
    __shared__ float hr[4][Dc];
    __shared__ float part[4][4][4][Dc];   // [kquart][rel][mat][col] = 32 KB
    int tid = threadIdx.x;
    int col = tid & 127, kq = tid >> 7;   // kq in 0..3
    int r0 = blockIdx.x * 4;              // 250 blocks * 4 = 1000
    hr[tid >> 7][tid & 127] = rel_table[(size_t)(r0 + (tid >> 7)) * Dc + (tid & 127)];
    __syncthreads();
    float aD[4] = {0}, a0[4] = {0}, a1[4] = {0}, a2[4] = {0};
    int i0 = kq * 32;
    #pragma unroll 4
    for (int ii = 0; ii < 32; ii++) {
        int i = i0 + ii;
        float wD = den_W1[i * Dc + col];
        float w0 = msg_W[(0 * 640 + 384 + i) * Dc + col];
        float w1 = msg_W[(1 * 640 + 384 + i) * Dc + col];
        float w2 = msg_W[(2 * 640 + 384 + i) * Dc + col];
        #pragma unroll
        for (int u = 0; u < 4; u++) {
            float h = hr[u][i];
            aD[u] += h * wD; a0[u] += h * w0; a1[u] += h * w1; a2[u] += h * w2;
        }
    }
    #pragma unroll
    for (int u = 0; u < 4; u++) {
        part[kq][u][0][col] = aD[u];
        part[kq][u][1][col] = a0[u];
        part[kq][u][2][col] = a1[u];
        part[kq][u][3][col] = a2[u];
    }
    __syncthreads();
    {
        int u = kq;
        int r = r0 + u;
        float sD = part[0][u][0][col] + part[1][u][0][col] + part[2][u][0][col] + part[3][u][0][col];
        float s0 = part[0][u][1][col] + part[1][u][1][col] + part[2][u][1][col] + part[3][u][1][col];
        float s1 = part[0][u][2][col] + part[1][u][2][col] + part[2][u][2][col] + part[3][u][2][col];
        float s2 = part[0][u][3][col] + part[1][u][3][col] + part[2][u][3][col] + part[3][u][3][col];
        g_relDen[r * Dc + col] = sD;
        g_relMsg[(0 * NRELc + r) * Dc + col] = s0 + msg_b[col];
        g_relMsg[(1 * NRELc + r) * Dc + col] = s1 + msg_b[Dc + col];
        g_relMsg[(2 * NRELc + r) * Dc + col] = s2 + msg_b[2 * Dc + col];
    }
    if (tid < 4) {
        float s = 0;
        for (int i = 0; i < Dc; i++) s += hr[tid][i] * beta_W[i];
        g_relBeta[r0 + tid] = s;
    } else if (tid < 16) {
        int t = tid - 4; int u = t / 3, k = t % 3;
        float s = 0;
        for (int i = 0; i < Dc; i++) s += hr[u][i] * att_W[k * 384 + 128 + i];
        g_relAtt[k * NRELc + (r0 + u)] = s;
    }
}

// ---------------- msg MMA: per-warp A staging (block syncs only around Bsm) ----------------
__global__ void __launch_bounds__(512, 1)
msg_mma_kernel(int k, const int* __restrict__ edge_index, const int* __restrict__ rels_g,
               const void* __restrict__ emk, const float* __restrict__ rel_table,
               const float* __restrict__ conf, const float* __restrict__ att_W,
               const float* __restrict__ scores, const void* __restrict__ ecm,
               const float* __restrict__ den_W2, const float* __restrict__ den_b2) {
    extern __shared__ char sm[];
    __nv_bfloat16* Ah = (__nv_bfloat16*)sm;
    __nv_bfloat16* Al = Ah + TILE * ASTRIDE;
    uint4* Bsm = (uint4*)(Al + TILE * ASTRIDE);
    __shared__ int s_src[TILE];
    __shared__ int s_rel[TILE];
    __shared__ float s_aw[128];
    int tid = threadIdx.x, w = tid >> 5, lane = tid & 31;
    int g = lane >> 2, tg = lane & 3;
    int e0 = blockIdx.x * TILE, b = e0 >> 15;
    int ebi0 = e0 & (Ec - 1);
    int R = w * 16;

    // per-warp: own src/rel (16 entries)
    if (lane < 16) {
        s_src[R + lane] = edge_index[(size_t)b * 2 * Ec + ebi0 + R + lane];
        s_rel[R + lane] = rels_g[e0 + R + lane];
    }
    if (tid < 128) s_aw[tid] = att_W[(size_t)k * 384 + tid];
    // coop: B1 = W1[k]
    for (int i = tid; i < 4096; i += 512) Bsm[i] = g_Wfrag[k * 4096 + i];
    __syncthreads();                       // B1 + s_aw ready (src/rel are warp-local)

    // ---- phase 1: per-warp stage A = h_src * h_r (own 16 rows), then MMA ----
    {
        int c4 = lane * 4;
        #pragma unroll
        for (int rr = 0; rr < 16; rr++) {
            int row = R + rr;
            float4 hv = *(const float4*)&g_h[((size_t)(b * Nc + s_src[row])) * Dc + c4];
            float4 rv = *(const float4*)&rel_table[(size_t)s_rel[row] * Dc + c4];
            float4 v = make_float4(hv.x * rv.x, hv.y * rv.y, hv.z * rv.z, hv.w * rv.w);
            unsigned short h[4], l[4];
            bsplit(v.x, h[0], l[0]); bsplit(v.y, h[1], l[1]);
            bsplit(v.z, h[2], l[2]); bsplit(v.w, h[3], l[3]);
            *(uint2*)&Ah[row * ASTRIDE + c4] = make_uint2((uint32_t)h[0] | ((uint32_t)h[1] << 16),
                                                          (uint32_t)h[2] | ((uint32_t)h[3] << 16));
            *(uint2*)&Al[row * ASTRIDE + c4] = make_uint2((uint32_t)l[0] | ((uint32_t)l[1] << 16),
                                                          (uint32_t)l[2] | ((uint32_t)l[3] << 16));
        }
    }
    __syncwarp();

    float d[16][4];
    #pragma unroll
    for (int t = 0; t < 16; t++) { d[t][0] = d[t][1] = d[t][2] = d[t][3] = 0.0f; }
    #pragma unroll
    for (int ks = 0; ks < 8; ks++) {
        int ko = ks * 16 + tg * 2;
        uint32_t ah0 = *(uint32_t*)&Ah[(R + g) * ASTRIDE + ko];
        uint32_t ah1 = *(uint32_t*)&Ah[(R + g + 8) * ASTRIDE + ko];
        uint32_t ah2 = *(uint32_t*)&Ah[(R + g) * ASTRIDE + ko + 8];
        uint32_t ah3 = *(uint32_t*)&Ah[(R + g + 8) * ASTRIDE + ko + 8];
        uint32_t al0 = *(uint32_t*)&Al[(R + g) * ASTRIDE + ko];
        uint32_t al1 = *(uint32_t*)&Al[(R + g + 8) * ASTRIDE + ko];
        uint32_t al2 = *(uint32_t*)&Al[(R + g) * ASTRIDE + ko + 8];
        uint32_t al3 = *(uint32_t*)&Al[(R + g + 8) * ASTRIDE + ko + 8];
        #pragma unroll
        for (int nt = 0; nt < 16; nt++) {
            uint4 bf = Bsm[(ks * 16 + nt) * 32 + lane];
            mma_bf16(d[nt][0], d[nt][1], d[nt][2], d[nt][3], ah0, ah1, ah2, ah3, bf.x, bf.y);
            mma_bf16(d[nt][0], d[nt][1], d[nt][2], d[nt][3], ah0, ah1, ah2, ah3, bf.z, bf.w);
            mma_bf16(d[nt][0], d[nt][1], d[nt][2], d[nt][3], al0, al1, al2, al3, bf.x, bf.y);
        }
    }
    __syncthreads();                       // everyone done with B1 before overwrite

    // ---- phase 2: coop B2 = W5[k]; per-warp stage A = conf (own rows) ----
    for (int i = tid; i < 4096; i += 512) Bsm[i] = g_Wfrag[(3 + k) * 4096 + i];
    {
        int c4 = lane * 4;
        #pragma unroll
        for (int rr = 0; rr < 16; rr++) {
            int row = R + rr;
            float4 v = *(const float4*)&conf[((size_t)(e0 + row)) * Dc + c4];
            unsigned short h[4], l[4];
            bsplit(v.x, h[0], l[0]); bsplit(v.y, h[1], l[1]);
            bsplit(v.z, h[2], l[2]); bsplit(v.w, h[3], l[3]);
            *(uint2*)&Ah[row * ASTRIDE + c4] = make_uint2((uint32_t)h[0] | ((uint32_t)h[1] << 16),
                                                          (uint32_t)h[2] | ((uint32_t)h[3] << 16));
            *(uint2*)&Al[row * ASTRIDE + c4] = make_uint2((uint32_t)l[0] | ((uint32_t)l[1] << 16),
                                                          (uint32_t)l[2] | ((uint32_t)l[3] << 16));
        }
    }
    __syncthreads();                       // B2 ready (A rows are warp-local)
    #pragma unroll
    for (int ks = 0; ks < 8; ks++) {
        int ko = ks * 16 + tg * 2;
        uint32_t ah0 = *(uint32_t*)&Ah[(R + g) * ASTRIDE + ko];
        uint32_t ah1 = *(uint32_t*)&Ah[(R + g + 8) * ASTRIDE + ko];
        uint32_t ah2 = *(uint32_t*)&Ah[(R + g) * ASTRIDE + ko + 8];
        uint32_t ah3 = *(uint32_t*)&Ah[(R + g + 8) * ASTRIDE + ko + 8];
        uint32_t al0 = *(uint32_t*)&Al[(R + g) * ASTRIDE + ko];
        uint32_t al1 = *(uint32_t*)&Al[(R + g + 8) * ASTRIDE + ko];
        uint32_t al2 = *(uint32_t*)&Al[(R + g) * ASTRIDE + ko + 8];
        uint32_t al3 = *(uint32_t*)&Al[(R + g + 8) * ASTRIDE + ko + 8];
        #pragma unroll
        for (int nt = 0; nt < 16; nt++) {
            uint4 bf = Bsm[(ks * 16 + nt) * 32 + lane];
            mma_bf16(d[nt][0], d[nt][1], d[nt][2], d[nt][3], ah0, ah1, ah2, ah3, bf.x, bf.y);
            mma_bf16(d[nt][0], d[nt][1], d[nt][2], d[nt][3], ah0, ah1, ah2, ah3, bf.z, bf.w);
            mma_bf16(d[nt][0], d[nt][1], d[nt][2], d[nt][3], al0, al1, al2, al3, bf.x, bf.y);
        }
    }

    // ---- epilogue: 2 rows per thread ----
    int r0 = R + g, r1 = R + g + 8;
    int ea = e0 + r0, eb = e0 + r1;
    int ra = s_rel[r0], rb = s_rel[r1];
    int sa = s_src[r0], sbn = s_src[r1];
    bool za = (sa == 0), zb = (sbn == 0);
    const float* rma = &g_relMsg[((size_t)k * NRELc + ra) * Dc];
    const float* rmb = &g_relMsg[((size_t)k * NRELc + rb) * Dc];
    const float* hwa = &g_hW2[((size_t)(b * Nc + sa)) * Dc];
    const float* hwb = &g_hW2[((size_t)(b * Nc + sbn)) * Dc];
    const float* z0t = &g_z0add[k * Dc];
    float pa = 0, pb = 0;
    #pragma unroll
    for (int nt = 0; nt < 16; nt++) {
        int col = nt * 8 + tg * 2;
        float2 ta = *(const float2*)&rma[col];
        float2 tb = *(const float2*)&rmb[col];
        float v0 = d[nt][0] + ta.x;
        float v1 = d[nt][1] + ta.y;
        float v2 = d[nt][2] + tb.x;
        float v3 = d[nt][3] + tb.y;
        if (k > 0) {
            float2 ha = *(const float2*)&hwa[col];
            float2 hb = *(const float2*)&hwb[col];
            v0 += ha.x; v1 += ha.y; v2 += hb.x; v3 += hb.y;
        }
        if (za || zb) {
            float2 zv = *(const float2*)&z0t[col];
            if (za) { v0 += zv.x; v1 += zv.y; }
            if (zb) { v2 += zv.x; v3 += zv.y; }
        }
        v0 = fmaxf(v0, 0.0f); v1 = fmaxf(v1, 0.0f);
        v2 = fmaxf(v2, 0.0f); v3 = fmaxf(v3, 0.0f);
        float aw0 = s_aw[col], aw1 = s_aw[col + 1];
        pa += v0 * aw0 + v1 * aw1;
        pb += v2 * aw0 + v3 * aw1;
        *(float2*)&g_raw[(size_t)ea * Dc + col] = make_float2(v0, v1);
        *(float2*)&g_raw[(size_t)eb * Dc + col] = make_float2(v2, v3);
    }
    pa += __shfl_xor_sync(0xffffffffu, pa, 1); pa += __shfl_xor_sync(0xffffffffu, pa, 2);
    pb += __shfl_xor_sync(0xffffffffu, pb, 1); pb += __shfl_xor_sync(0xffffffffu, pb, 2);
    if (tg == 0) {
        int es[2] = {ea, eb};
        int rr2[2] = {ra, rb};
        float ps[2] = {pa, pb};
        #pragma unroll
        for (int q = 0; q < 2; q++) {
            int e = es[q];
            float att = ps[q] + g_relAtt[k * NRELc + rr2[q]] + g_rqAtt[k * Bc + b];
            att = att > 0.0f ? att : 0.01f * att;
            float ex = ldmask(emk, e) ? __expf(att) : 0.0f;
            g_att[e] = ex;
            int tgt = edge_index[(size_t)(b * 2 + 1) * Ec + (e & (Ec - 1))];
            if (ex != 0.0f) atomicAdd(&g_sm[b * Nc + tgt], ex);
        }
    }

    // ---- phase 3 (k == 0 only): conf @ A3 -> den/gate (conf still staged in Ah/Al) ----
    if (k == 0) {
        __syncthreads();    // all warps done reading B2
        for (int i = tid; i < 4096; i += 512) Bsm[i] = g_Wfrag[6 * 4096 + i];
        __syncthreads();
        #pragma unroll
        for (int t = 0; t < 16; t++) { d[t][0] = d[t][1] = d[t][2] = d[t][3] = 0.0f; }
        #pragma unroll
        for (int ks = 0; ks < 8; ks++) {
            int ko = ks * 16 + tg * 2;
            uint32_t ah0 = *(uint32_t*)&Ah[(R + g) * ASTRIDE + ko];
            uint32_t ah1 = *(uint32_t*)&Ah[(R + g + 8) * ASTRIDE + ko];
            uint32_t ah2 = *(uint32_t*)&Ah[(R + g) * ASTRIDE + ko + 8];
            uint32_t ah3 = *(uint32_t*)&Ah[(R + g + 8) * ASTRIDE + ko + 8];
            uint32_t al0 = *(uint32_t*)&Al[(R + g) * ASTRIDE + ko];
            uint32_t al1 = *(uint32_t*)&Al[(R + g + 8) * ASTRIDE + ko];
            uint32_t al2 = *(uint32_t*)&Al[(R + g) * ASTRIDE + ko + 8];
            uint32_t al3 = *(uint32_t*)&Al[(R + g + 8) * ASTRIDE + ko + 8];
            #pragma unroll
            for (int nt = 0; nt < 16; nt++) {
                uint4 bf = Bsm[(ks * 16 + nt) * 32 + lane];
                mma_bf16(d[nt][0], d[nt][1], d[nt][2], d[nt][3], ah0, ah1, ah2, ah3, bf.x, bf.y);
                mma_bf16(d[nt][0], d[nt][1], d[nt][2], d[nt][3], ah0, ah1, ah2, ah3, bf.z, bf.w);
                mma_bf16(d[nt][0], d[nt][1], d[nt][2], d[nt][3], al0, al1, al2, al3, bf.x, bf.y);
            }
        }
        const float* qd = &g_rqDen[b * Dc];
        float sda = 0, sdb = 0;
        #pragma unroll
        for (int nt = 0; nt < 16; nt++) {
            int col = nt * 8 + tg * 2;
            float2 qv = *(const float2*)&qd[col];
            float2 da = *(const float2*)&g_relDen[ra * Dc + col];
            float2 db = *(const float2*)&g_relDen[rb * Dc + col];
            float2 w2 = *(const float2*)&den_W2[col];
            sda += fmaxf(d[nt][0] + da.x + qv.x, 0.0f) * w2.x
                 + fmaxf(d[nt][1] + da.y + qv.y, 0.0f) * w2.y;
            sdb += fmaxf(d[nt][2] + db.x + qv.x, 0.0f) * w2.x
                 + fmaxf(d[nt][3] + db.y + qv.y, 0.0f) * w2.y;
        }
        sda += __shfl_xor_sync(0xffffffffu, sda, 1); sda += __shfl_xor_sync(0xffffffffu, sda, 2);
        sdb += __shfl_xor_sync(0xffffffffu, sdb, 1); sdb += __shfl_xor_sync(0xffffffffu, sdb, 2);
        if (tg == 0) {
            float bv = den_b2[0];
            int es[2] = {ea, eb};
            float ss[2] = {sda, sdb};
            int rr2[2] = {ra, rb};
            #pragma unroll
            for (int q = 0; q < 2; q++) {
                int e = es[q], rel = rr2[q];
                float den = sgm(ss[q] + bv);
                den *= ldmask(emk, e) ? 1.0f : 0.0f;
                float beta = sgm(g_relBeta[rel] + g_rqBeta[b]);
                float gate = ldmask(ecm, e) ? sgm((scores[e] - beta) * 10.0f) : 0.5f;
                g_gd[e] = gate * den;
            }
        }
    }
}

// ---------------- K3: weighted message scatter ----------------
__global__ void scatter_kernel(const int* __restrict__ edge_index) {
    int gt = blockIdx.x * blockDim.x + threadIdx.x;
    int glob = gt >> 5;
    int l = threadIdx.x & 31;
    if (glob >= BEc) return;
    int b = glob >> 15, ebi = glob & (Ec - 1);
    float wv = 0.0f;
    int tgt = 0;
    if (l == 0) {
        tgt = edge_index[(size_t)(b * 2 + 1) * Ec + ebi];
        float gd = g_gd[glob];
        if (gd != 0.0f) {
            float ex = g_att[glob];
            if (ex != 0.0f) {
                float sden = g_sm[b * Nc + tgt];
                wv = gd * ex / (sden + 1e-8f);
            }
        }
    }
    wv  = __shfl_sync(0xffffffffu, wv, 0);
    tgt = __shfl_sync(0xffffffffu, tgt, 0);
    if (wv != 0.0f) {
        float4 rm = *(const float4*)&g_raw[((size_t)glob) * Dc + 4 * l];
        float4 v = make_float4(wv * rm.x, wv * rm.y, wv * rm.z, wv * rm.w);
        red_v4(&g_aggr[((size_t)(b * Nc + tgt)) * Dc + 4 * l], v);
    }
}

// ---------------- K4: update GEMM + LN (+ reset + fused hW2 for next layer) ----------------
__global__ void __launch_bounds__(256, 1)
upd_kernel(int k, int doNext, const float* __restrict__ upd_W, const float* __restrict__ upd_b,
           const float* __restrict__ ln_g, const float* __restrict__ ln_b,
           const float* __restrict__ msg_W, float* __restrict__ out) {
    extern __shared__ float smemf[];
    float* Ws = smemf;
    float* Ag = smemf + 128 * INSTRIDE;
    __shared__ float mus[64], rst[64];
    int tid = threadIdx.x;
    int w = tid >> 5, l = tid & 31;
    int n0 = blockIdx.x * 64;
    #pragma unroll
    for (int rr = 0; rr < 16; rr++) {
        int kk = w * 16 + rr;
        *(float4*)&Ws[kk * INSTRIDE + 4 * l] = *(const float4*)&upd_W[((size_t)k * Dc + kk) * Dc + 4 * l];
    }
    #pragma unroll
    for (int rr = 0; rr < 8; rr++) {
        int nl = w * 8 + rr;
        *(float4*)&Ag[nl * INSTRIDE + 4 * l] = *(const float4*)&g_aggr[((size_t)(n0 + nl)) * Dc + 4 * l];
    }
    __syncthreads();
    int ty = tid >> 4, tx = tid & 15;
    unsigned long long acc[4][4] = {};
    #pragma unroll 2
    for (int kk4 = 0; kk4 < Dc; kk4 += 4) {
        float avv[4][4];
        #pragma unroll
        for (int r = 0; r < 4; r++)
            *(float4*)avv[r] = *(const float4*)&Ag[(ty * 4 + r) * INSTRIDE + kk4];
        #pragma unroll
        for (int u = 0; u < 4; u++) {
            const ulonglong2* wp = (const ulonglong2*)&Ws[(kk4 + u) * INSTRIDE + tx * 8];
            ulonglong2 wa = wp[0], wb = wp[1];
            #pragma unroll
            for (int r = 0; r < 4; r++) {
                unsigned long long a2 = packdup(avv[r][u]);
                FMA2(acc[r][0], a2, wa.x); FMA2(acc[r][1], a2, wa.y);
                FMA2(acc[r][2], a2, wb.x); FMA2(acc[r][3], a2, wb.y);
            }
        }
    }
    __syncthreads();

    float vbuf[4][8];
    float s1[4] = {0}, s2[4] = {0};
    #pragma unroll
    for (int r = 0; r < 4; r++) {
        int n = n0 + ty * 4 + r;
        float vout[8];
        #pragma unroll
        for (int q = 0; q < 4; q++) { float2 u = unpk(acc[r][q]); vout[2*q] = u.x; vout[2*q+1] = u.y; }
        #pragma unroll
        for (int c = 0; c < 8; c++) {
            int j = tx * 8 + c;
            float v = g_h[((size_t)n) * Dc + j] + vout[c] + upd_b[k * Dc + j];
            vbuf[r][c] = v;
            s1[r] += v;
            s2[r] += v * v;
        }
    }
    float* red1 = Ag;
    float* red2 = Ag + 64 * 17;
    #pragma unroll
    for (int r = 0; r < 4; r++) {
        red1[(ty * 4 + r) * 17 + tx] = s1[r];
        red2[(ty * 4 + r) * 17 + tx] = s2[r];
    }
    __syncthreads();
    if (tid < 64) {
        float a = 0, bb = 0;
        #pragma unroll
        for (int t = 0; t < 16; t++) { a += red1[tid * 17 + t]; bb += red2[tid * 17 + t]; }
        float mu = a * (1.0f / Dc);
        float var = bb * (1.0f / Dc) - mu * mu;
        mus[tid] = mu;
        rst[tid] = rsqrtf(var + 1e-5f);
    }
    __syncthreads();
    #pragma unroll
    for (int r = 0; r < 4; r++) {
        int nl = ty * 4 + r;
        int n = n0 + nl;
        float mu = mus[nl], rs = rst[nl];
        float y[8];
        #pragma unroll
        for (int c = 0; c < 8; c++) {
            int j = tx * 8 + c;
            y[c] = (vbuf[r][c] - mu) * rs * ln_g[j] + ln_b[j];
        }
        *(float4*)&g_h[((size_t)n) * Dc + tx * 8]     = make_float4(y[0], y[1], y[2], y[3]);
        *(float4*)&g_h[((size_t)n) * Dc + tx * 8 + 4] = make_float4(y[4], y[5], y[6], y[7]);
        *(float4*)&Ag[nl * INSTRIDE + tx * 8]     = make_float4(y[0], y[1], y[2], y[3]);
        *(float4*)&Ag[nl * INSTRIDE + tx * 8 + 4] = make_float4(y[4], y[5], y[6], y[7]);
        if ((n & (Nc - 1)) == 0) {
            int b = n >> 11;
            #pragma unroll
            for (int c = 0; c < 8; c++) out[((size_t)b * Lc + k) * Dc + tx * 8 + c] = y[c];
        }
    }

    if (doNext) {
        float4 z = make_float4(0, 0, 0, 0);
        #pragma unroll
        for (int rr = 0; rr < 8; rr++) {
            int nl = w * 8 + rr;
            *(float4*)&g_aggr[((size_t)(n0 + nl)) * Dc + 4 * l] = z;
        }
        if (tid < 64) g_sm[n0 + tid] = 0.0f;
        __syncthreads();
        #pragma unroll
        for (int rr = 0; rr < 16; rr++) {
            int kk = w * 16 + rr;
            *(float4*)&Ws[kk * INSTRIDE + 4 * l] =
                *(const float4*)&msg_W[((size_t)(k + 1) * 640 + 128 + kk) * Dc + 4 * l];
        }
        __syncthreads();
        unsigned long long acc2[4][4] = {};
        #pragma unroll 2
        for (int kk4 = 0; kk4 < Dc; kk4 += 4) {
            float avv[4][4];
            #pragma unroll
            for (int r = 0; r < 4; r++)
                *(float4*)avv[r] = *(const float4*)&Ag[(ty * 4 + r) * INSTRIDE + kk4];
            #pragma unroll
            for (int u = 0; u < 4; u++) {
                const ulonglong2* wp = (const ulonglong2*)&Ws[(kk4 + u) * INSTRIDE + tx * 8];
                ulonglong2 wa = wp[0], wb = wp[1];
                #pragma unroll
                for (int r = 0; r < 4; r++) {
                    unsigned long long a2 = packdup(avv[r][u]);
                    FMA2(acc2[r][0], a2, wa.x); FMA2(acc2[r][1], a2, wa.y);
                    FMA2(acc2[r][2], a2, wb.x); FMA2(acc2[r][3], a2, wb.y);
                }
            }
        }
        #pragma unroll
        for (int r = 0; r < 4; r++) {
            int n = n0 + ty * 4 + r;
            float vout[8];
            #pragma unroll
            for (int q = 0; q < 4; q++) { float2 u = unpk(acc2[r][q]); vout[2*q] = u.x; vout[2*q+1] = u.y; }
            *(float4*)&g_hW2[((size_t)n) * Dc + tx * 8]     = make_float4(vout[0], vout[1], vout[2], vout[3]);
            *(float4*)&g_hW2[((size_t)n) * Dc + tx * 8 + 4] = make_float4(vout[4], vout[5], vout[6], vout[7]);
        }
    }
}

// ---------------- launch ----------------
extern "C" void kernel_launch(void* const* d_in, const int* in_sizes, int n_in,
                              void* d_out, int out_size) {
    const int*   edge_index = (const int*)d_in[0];
    const int*   rels       = (const int*)d_in[1];
    const float* scores     = (const float*)d_in[2];
    const void*  ecm        = d_in[3];
    const void*  emk        = d_in[4];
    // d_in[5] = mask (unused)
    const float* rq         = (const float*)d_in[6];
    const float* conf       = (const float*)d_in[7];
    const float* rel_table  = (const float*)d_in[8];
    const float* beta_W     = (const float*)d_in[9];
    const float* beta_b     = (const float*)d_in[10];
    const float* msg_W      = (const float*)d_in[11];
    const float* msg_b      = (const float*)d_in[12];
    const float* upd_W      = (const float*)d_in[13];
    const float* upd_b      = (const float*)d_in[14];
    const float* ln_g       = (const float*)d_in[15];
    const float* ln_b       = (const float*)d_in[16];
    const float* att_W      = (const float*)d_in[17];
    const float* att_b      = (const float*)d_in[18];
    const float* den_W1     = (const float*)d_in[19];
    const float* den_b1     = (const float*)d_in[20];
    const float* den_W2     = (const float*)d_in[21];
    const float* den_b2     = (const float*)d_in[22];
    float* out = (float*)d_out;

    cudaFuncSetAttribute(msg_mma_kernel, cudaFuncAttributeMaxDynamicSharedMemorySize, SMEM_MMA);
    cudaFuncSetAttribute(upd_kernel,     cudaFuncAttributeMaxDynamicSharedMemorySize, SMEM_UPD);

    init_all_kernel<<<(Bc * Nc * Dc) / 256, 256>>>((const unsigned*)emk);
    prep_combo_kernel<<<120, 256>>>(msg_W, den_W1, rq, den_b1, beta_W, beta_b, att_W, att_b);
    rel_tables_kernel<<<250, 512>>>(rel_table, den_W1, msg_W, msg_b, beta_W, att_W);

    for (int k = 0; k < Lc; k++) {
        msg_mma_kernel<<<BEc / TILE, 512, SMEM_MMA>>>(k, edge_index, rels, emk, rel_table,
                                                      conf, att_W, scores, ecm, den_W2, den_b2);
        scatter_kernel<<<(BEc * 32) / 256, 256>>>(edge_index);
        upd_kernel<<<(Bc * Nc) / 64, 256, SMEM_UPD>>>(k, (k < Lc - 1) ? 1 : 0,
                                                      upd_W, upd_b, ln_g, ln_b, msg_W, out);
    }
}

// round 16
// speedup vs baseline: 1.0536x; 1.0166x over previous
#include <cuda_runtime.h>
#include <cuda_bf16.h>
#include <cstdint>
#include <cstddef>

#define Bc 4
#define Nc 2048
#define Ec 32768
#define Dc 128
#define Lc 3
#define NRELc 1000
#define BEc (Bc*Ec)          // 131072 edges

// ---------------- static device scratch ----------------
__device__ float    g_h[Bc*Nc*Dc];
__device__ float    g_aggr[Bc*Nc*Dc];
__device__ float    g_sm[Bc*Nc];
__device__ float    g_raw[(size_t)BEc*Dc];    // 64 MB fp32
__device__ float    g_att[BEc];               // holds exp(att)
__device__ float    g_gd[BEc];
__device__ float    g_relMsg[Lc*NRELc*Dc];    // h_r@W4 + msg_b
__device__ float    g_relDen[NRELc*Dc];
__device__ float    g_relBeta[NRELc];
__device__ float    g_relAtt[Lc*NRELc];
__device__ float    g_rqDen[Bc*Dc];
__device__ float    g_rqBeta[Bc];
__device__ float    g_rqAtt[Lc*Bc];
__device__ float    g_z0add[Lc*Dc];           // colsum(W3[k]) + (k==0)*colsum(W2[0])
__device__ float    g_hW2[Bc*Nc*Dc];          // h @ W2[k]   (layers 1,2)
__device__ uint2    g_Wfrag[7*8192];          // fragment-packed tf32 weights
__device__ int      g_mflag = 0;              // zero-init; only OR'd with 1 (deterministic)

// ---------------- helpers ----------------
__device__ __forceinline__ float sgm(float x) { return 1.0f / (1.0f + __expf(-x)); }
__device__ __forceinline__ int ldmask(const void* p, int i) {
    return g_mflag ? (int)((const unsigned char*)p)[i] : ((const int*)p)[i];
}
__device__ __forceinline__ unsigned long long packdup(float a) {
    unsigned long long r; unsigned u = __float_as_uint(a);
    asm("mov.b64 %0, {%1, %1};" : "=l"(r) : "r"(u));
    return r;
}
__device__ __forceinline__ float2 unpk(unsigned long long v) {
    float2 f;
    asm("mov.b64 {%0, %1}, %2;" : "=f"(f.x), "=f"(f.y) : "l"(v));
    return f;
}
#define FMA2(acc, a, b) asm("fma.rn.f32x2 %0, %1, %2, %0;" : "+l"(acc) : "l"(a), "l"(b))
__device__ __forceinline__ void red_v4(float* p, float4 v) {
    asm volatile("red.global.add.v4.f32 [%0], {%1,%2,%3,%4};"
                 :: "l"(p), "f"(v.x), "f"(v.y), "f"(v.z), "f"(v.w) : "memory");
}
__device__ __forceinline__ uint32_t f2tf(float x) {
    uint32_t r; asm("cvt.rna.tf32.f32 %0, %1;" : "=r"(r) : "f"(x)); return r;
}
__device__ __forceinline__ void mma_tf32(float& d0, float& d1, float& d2, float& d3,
                                         uint32_t a0, uint32_t a1, uint32_t a2, uint32_t a3,
                                         uint32_t b0, uint32_t b1) {
    asm volatile(
        "mma.sync.aligned.m16n8k8.row.col.f32.tf32.tf32.f32 "
        "{%0,%1,%2,%3}, {%4,%5,%6,%7}, {%8,%9}, {%0,%1,%2,%3};"
        : "+f"(d0), "+f"(d1), "+f"(d2), "+f"(d3)
        : "r"(a0), "r"(a1), "r"(a2), "r"(a3), "r"(b0), "r"(b1));
}

#define INSTRIDE 132
#define SMEM_UPD ((128*INSTRIDE + 64*INSTRIDE)*4)
#define ASTRF 132                                  // fp32/tf32 A row stride (floats)
#define TILE 256                                   // edges per MMA block
#define SMEM_MMA (TILE*ASTRF*4 + 8192*8)           // 135168 + 65536 = 200704 B

// ---------------- upfront init (layer 0 state + mask detect) ----------------
__global__ void init_all_kernel(const unsigned* __restrict__ emk32) {
    int idx = blockIdx.x * 256 + threadIdx.x;
    g_aggr[idx] = 0.0f;
    int n = (idx >> 7) & (Nc - 1);
    g_h[idx] = (n == 0) ? 1.0f : 0.0f;
    if (idx < Bc * Nc) g_sm[idx] = 0.0f;
    if (idx < BEc / 4) {                      // 32768 words = BEc bytes
        if (emk32[idx] & 0xFFFFFF00u) atomicOr(&g_mflag, 1);
    }
}

// ---------------- prep combo: tf32 weight fragments (blk<224) + batch vectors ----------------
// wfrag tiles: 0..2 = W1[k], 3..5 = W5[k], 6 = A3 (den_W1 rows 256..383)
// m16n8k8 B frag: b0 = B[k = ks*8 + tg][n = nt*8 + g], b1 = B[k+4][n]
__global__ void prep_combo_kernel(const float* __restrict__ msg_W,
                                  const float* __restrict__ den_W1,
                                  const float* __restrict__ rq,
                                  const float* __restrict__ den_b1,
                                  const float* __restrict__ beta_W,
                                  const float* __restrict__ beta_b,
                                  const float* __restrict__ att_W,
                                  const float* __restrict__ att_b) {
    if (blockIdx.x < 224) {
        int idx = blockIdx.x * 256 + threadIdx.x;   // 7*8192
        int tile = idx >> 13;
        int r = idx & 8191;
        int ks = r >> 9;                 // 0..15
        int nt = (r >> 5) & 15;
        int lane = r & 31;
        int g = lane >> 2, tg = lane & 3;
        int n = nt * 8 + g;
        int k0 = ks * 8 + tg;
        const float* base;
        if (tile < 3)      base = msg_W + ((size_t)tile * 640) * Dc;
        else if (tile < 6) base = msg_W + ((size_t)(tile - 3) * 640 + 512) * Dc;
        else               base = den_W1 + (size_t)256 * Dc;
        uint32_t b0 = f2tf(base[(size_t)k0 * Dc + n]);
        uint32_t b1 = f2tf(base[(size_t)(k0 + 4) * Dc + n]);
        g_Wfrag[idx] = make_uint2(b0, b1);
        return;
    }
    int blk = blockIdx.x - 224;                 // 0..7
    int j = threadIdx.x;
    if (j >= 128) return;
    if (blk < 4) {
        int b = blk;
        float acc = 0;
        for (int i = 0; i < Dc; i++) acc += rq[b * Dc + i] * den_W1[(Dc + i) * Dc + j];
        g_rqDen[b * Dc + j] = acc + den_b1[j];
    } else if (blk < 7) {
        int k = blk - 4;
        float s = 0;
        for (int i = 0; i < Dc; i++) s += msg_W[(k * 640 + 256 + i) * Dc + j];
        if (k == 0)
            for (int i = 0; i < Dc; i++) s += msg_W[(0 * 640 + 128 + i) * Dc + j];
        g_z0add[k * Dc + j] = s;
    } else {
        if (j < Bc) {
            float s = 0;
            for (int i = 0; i < Dc; i++) s += rq[j * Dc + i] * beta_W[i];
            g_rqBeta[j] = s + beta_b[0];
        }
        if (j < Lc * Bc) {
            int k = j / Bc, b = j % Bc;
            float s = 0;
            for (int i = 0; i < Dc; i++) s += rq[b * Dc + i] * att_W[k * 384 + 256 + i];
            g_rqAtt[k * Bc + b] = s + att_b[k];
        }
    }
}

// ---------------- P0: per-relation tables (4-way K split, 512 threads) ----------------
__global__ void __launch_bounds__(512, 1)
rel_tables_kernel(const float* __restrict__ rel_table,
                  const float* __restrict__ den_W1,
                  const float* __restrict__ msg_W,
                  const float* __restrict__ msg_b,
                  const float* __restrict__ beta_W,
                  const float* __restrict__ att_W) {
    __shared__ float hr[4][Dc];
    __shared__ float part[4][4][4][Dc];   // [kquart][rel][mat][col] = 32 KB
    int tid = threadIdx.x;
    int col = tid & 127, kq = tid >> 7;   // kq in 0..3
    int r0 = blockIdx.x * 4;              // 250 blocks * 4 = 1000
    hr[tid >> 7][tid & 127] = rel_table[(size_t)(r0 + (tid >> 7)) * Dc + (tid & 127)];
    __syncthreads();
    float aD[4] = {0}, a0[4] = {0}, a1[4] = {0}, a2[4] = {0};
    int i0 = kq * 32;
    #pragma unroll 4
    for (int ii = 0; ii < 32; ii++) {
        int i = i0 + ii;
        float wD = den_W1[i * Dc + col];
        float w0 = msg_W[(0 * 640 + 384 + i) * Dc + col];
        float w1 = msg_W[(1 * 640 + 384 + i) * Dc + col];
        float w2 = msg_W[(2 * 640 + 384 + i) * Dc + col];
        #pragma unroll
        for (int u = 0; u < 4; u++) {
            float h = hr[u][i];
            aD[u] += h * wD; a0[u] += h * w0; a1[u] += h * w1; a2[u] += h * w2;
        }
    }
    #pragma unroll
    for (int u = 0; u < 4; u++) {
        part[kq][u][0][col] = aD[u];
        part[kq][u][1][col] = a0[u];
        part[kq][u][2][col] = a1[u];
        part[kq][u][3][col] = a2[u];
    }
    __syncthreads();
    {
        int u = kq;
        int r = r0 + u;
        float sD = part[0][u][0][col] + part[1][u][0][col] + part[2][u][0][col] + part[3][u][0][col];
        float s0 = part[0][u][1][col] + part[1][u][1][col] + part[2][u][1][col] + part[3][u][1][col];
        float s1 = part[0][u][2][col] + part[1][u][2][col] + part[2][u][2][col] + part[3][u][2][col];
        float s2 = part[0][u][3][col] + part[1][u][3][col] + part[2][u][3][col] + part[3][u][3][col];
        g_relDen[r * Dc + col] = sD;
        g_relMsg[(0 * NRELc + r) * Dc + col] = s0 + msg_b[col];
        g_relMsg[(1 * NRELc + r) * Dc + col] = s1 + msg_b[Dc + col];
        g_relMsg[(2 * NRELc + r) * Dc + col] = s2 + msg_b[2 * Dc + col];
    }
    if (tid < 4) {
        float s = 0;
        for (int i = 0; i < Dc; i++) s += hr[tid][i] * beta_W[i];
        g_relBeta[r0 + tid] = s;
    } else if (tid < 16) {
        int t = tid - 4; int u = t / 3, k = t % 3;
        float s = 0;
        for (int i = 0; i < Dc; i++) s += hr[u][i] * att_W[k * 384 + 128 + i];
        g_relAtt[k * NRELc + (r0 + u)] = s;
    }
}

// ---------------- msg MMA (tf32 single-pass): phase1 (h.h_r)@W1 + phase2 conf@W5 (+ phase3 at k=0) ----------------
__global__ void __launch_bounds__(512, 1)
msg_mma_kernel(int k, const int* __restrict__ edge_index, const int* __restrict__ rels_g,
               const void* __restrict__ emk, const float* __restrict__ rel_table,
               const float* __restrict__ conf, const float* __restrict__ att_W,
               const float* __restrict__ scores, const void* __restrict__ ecm,
               const float* __restrict__ den_W2, const float* __restrict__ den_b2) {
    extern __shared__ char sm[];
    float* As = (float*)sm;                         // TILE x 132 tf32-rounded floats
    uint2* Bsm = (uint2*)(sm + TILE * ASTRF * 4);   // 8192 uint2
    __shared__ int s_src[TILE];
    __shared__ int s_rel[TILE];
    __shared__ float s_aw[128];
    int tid = threadIdx.x, w = tid >> 5, lane = tid & 31;
    int g = lane >> 2, tg = lane & 3;
    int e0 = blockIdx.x * TILE, b = e0 >> 15;
    int ebi0 = e0 & (Ec - 1);
    int R = w * 16;

    // per-warp: own src/rel (16 entries)
    if (lane < 16) {
        s_src[R + lane] = edge_index[(size_t)b * 2 * Ec + ebi0 + R + lane];
        s_rel[R + lane] = rels_g[e0 + R + lane];
    }
    if (tid < 128) s_aw[tid] = att_W[(size_t)k * 384 + tid];
    for (int i = tid; i < 8192; i += 512) Bsm[i] = g_Wfrag[k * 8192 + i];
    __syncthreads();                       // B1 + s_aw ready

    // ---- phase 1: per-warp stage A = tf32(h_src * h_r) (own 16 rows) ----
    {
        int c4 = lane * 4;
        #pragma unroll
        for (int rr = 0; rr < 16; rr++) {
            int row = R + rr;
            float4 hv = *(const float4*)&g_h[((size_t)(b * Nc + s_src[row])) * Dc + c4];
            float4 rv = *(const float4*)&rel_table[(size_t)s_rel[row] * Dc + c4];
            float4 t = make_float4(__uint_as_float(f2tf(hv.x * rv.x)),
                                   __uint_as_float(f2tf(hv.y * rv.y)),
                                   __uint_as_float(f2tf(hv.z * rv.z)),
                                   __uint_as_float(f2tf(hv.w * rv.w)));
            *(float4*)&As[row * ASTRF + c4] = t;
        }
    }
    __syncwarp();

    float d[16][4];
    #pragma unroll
    for (int t = 0; t < 16; t++) { d[t][0] = d[t][1] = d[t][2] = d[t][3] = 0.0f; }
    #pragma unroll
    for (int ks = 0; ks < 16; ks++) {
        int ko = ks * 8 + tg;
        uint32_t a0 = __float_as_uint(As[(R + g) * ASTRF + ko]);
        uint32_t a1 = __float_as_uint(As[(R + g + 8) * ASTRF + ko]);
        uint32_t a2 = __float_as_uint(As[(R + g) * ASTRF + ko + 4]);
        uint32_t a3 = __float_as_uint(As[(R + g + 8) * ASTRF + ko + 4]);
        #pragma unroll
        for (int nt = 0; nt < 16; nt++) {
            uint2 bf = Bsm[(ks * 16 + nt) * 32 + lane];
            mma_tf32(d[nt][0], d[nt][1], d[nt][2], d[nt][3], a0, a1, a2, a3, bf.x, bf.y);
        }
    }
    __syncthreads();                       // everyone done with B1 before overwrite

    // ---- phase 2: coop B2 = W5[k]; per-warp stage A = tf32(conf) ----
    for (int i = tid; i < 8192; i += 512) Bsm[i] = g_Wfrag[(3 + k) * 8192 + i];
    {
        int c4 = lane * 4;
        #pragma unroll
        for (int rr = 0; rr < 16; rr++) {
            int row = R + rr;
            float4 v = *(const float4*)&conf[((size_t)(e0 + row)) * Dc + c4];
            float4 t = make_float4(__uint_as_float(f2tf(v.x)), __uint_as_float(f2tf(v.y)),
                                   __uint_as_float(f2tf(v.z)), __uint_as_float(f2tf(v.w)));
            *(float4*)&As[row * ASTRF + c4] = t;
        }
    }
    __syncthreads();                       // B2 ready (A rows warp-local)
    #pragma unroll
    for (int ks = 0; ks < 16; ks++) {
        int ko = ks * 8 + tg;
        uint32_t a0 = __float_as_uint(As[(R + g) * ASTRF + ko]);
        uint32_t a1 = __float_as_uint(As[(R + g + 8) * ASTRF + ko]);
        uint32_t a2 = __float_as_uint(As[(R + g) * ASTRF + ko + 4]);
        uint32_t a3 = __float_as_uint(As[(R + g + 8) * ASTRF + ko + 4]);
        #pragma unroll
        for (int nt = 0; nt < 16; nt++) {
            uint2 bf = Bsm[(ks * 16 + nt) * 32 + lane];
            mma_tf32(d[nt][0], d[nt][1], d[nt][2], d[nt][3], a0, a1, a2, a3, bf.x, bf.y);
        }
    }

    // ---- epilogue: 2 rows per thread ----
    int r0 = R + g, r1 = R + g + 8;
    int ea = e0 + r0, eb = e0 + r1;
    int ra = s_rel[r0], rb = s_rel[r1];
    int sa = s_src[r0], sbn = s_src[r1];
    bool za = (sa == 0), zb = (sbn == 0);
    const float* rma = &g_relMsg[((size_t)k * NRELc + ra) * Dc];
    const float* rmb = &g_relMsg[((size_t)k * NRELc + rb) * Dc];
    const float* hwa = &g_hW2[((size_t)(b * Nc + sa)) * Dc];
    const float* hwb = &g_hW2[((size_t)(b * Nc + sbn)) * Dc];
    const float* z0t = &g_z0add[k * Dc];
    float pa = 0, pb = 0;
    #pragma unroll
    for (int nt = 0; nt < 16; nt++) {
        int col = nt * 8 + tg * 2;
        float2 ta = *(const float2*)&rma[col];
        float2 tb = *(const float2*)&rmb[col];
        float v0 = d[nt][0] + ta.x;
        float v1 = d[nt][1] + ta.y;
        float v2 = d[nt][2] + tb.x;
        float v3 = d[nt][3] + tb.y;
        if (k > 0) {
            float2 ha = *(const float2*)&hwa[col];
            float2 hb = *(const float2*)&hwb[col];
            v0 += ha.x; v1 += ha.y; v2 += hb.x; v3 += hb.y;
        }
        if (za || zb) {
            float2 zv = *(const float2*)&z0t[col];
            if (za) { v0 += zv.x; v1 += zv.y; }
            if (zb) { v2 += zv.x; v3 += zv.y; }
        }
        v0 = fmaxf(v0, 0.0f); v1 = fmaxf(v1, 0.0f);
        v2 = fmaxf(v2, 0.0f); v3 = fmaxf(v3, 0.0f);
        float aw0 = s_aw[col], aw1 = s_aw[col + 1];
        pa += v0 * aw0 + v1 * aw1;
        pb += v2 * aw0 + v3 * aw1;
        *(float2*)&g_raw[(size_t)ea * Dc + col] = make_float2(v0, v1);
        *(float2*)&g_raw[(size_t)eb * Dc + col] = make_float2(v2, v3);
    }
    pa += __shfl_xor_sync(0xffffffffu, pa, 1); pa += __shfl_xor_sync(0xffffffffu, pa, 2);
    pb += __shfl_xor_sync(0xffffffffu, pb, 1); pb += __shfl_xor_sync(0xffffffffu, pb, 2);
    if (tg == 0) {
        int es[2] = {ea, eb};
        int rr2[2] = {ra, rb};
        float ps[2] = {pa, pb};
        #pragma unroll
        for (int q = 0; q < 2; q++) {
            int e = es[q];
            float att = ps[q] + g_relAtt[k * NRELc + rr2[q]] + g_rqAtt[k * Bc + b];
            att = att > 0.0f ? att : 0.01f * att;
            float ex = ldmask(emk, e) ? __expf(att) : 0.0f;
            g_att[e] = ex;
            int tgt = edge_index[(size_t)(b * 2 + 1) * Ec + (e & (Ec - 1))];
            if (ex != 0.0f) atomicAdd(&g_sm[b * Nc + tgt], ex);
        }
    }

    // ---- phase 3 (k == 0 only): conf @ A3 -> den/gate (conf still staged in As) ----
    if (k == 0) {
        __syncthreads();    // all warps done reading B2
        for (int i = tid; i < 8192; i += 512) Bsm[i] = g_Wfrag[6 * 8192 + i];
        __syncthreads();
        #pragma unroll
        for (int t = 0; t < 16; t++) { d[t][0] = d[t][1] = d[t][2] = d[t][3] = 0.0f; }
        #pragma unroll
        for (int ks = 0; ks < 16; ks++) {
            int ko = ks * 8 + tg;
            uint32_t a0 = __float_as_uint(As[(R + g) * ASTRF + ko]);
            uint32_t a1 = __float_as_uint(As[(R + g + 8) * ASTRF + ko]);
            uint32_t a2 = __float_as_uint(As[(R + g) * ASTRF + ko + 4]);
            uint32_t a3 = __float_as_uint(As[(R + g + 8) * ASTRF + ko + 4]);
            #pragma unroll
            for (int nt = 0; nt < 16; nt++) {
                uint2 bf = Bsm[(ks * 16 + nt) * 32 + lane];
                mma_tf32(d[nt][0], d[nt][1], d[nt][2], d[nt][3], a0, a1, a2, a3, bf.x, bf.y);
            }
        }
        const float* qd = &g_rqDen[b * Dc];
        float sda = 0, sdb = 0;
        #pragma unroll
        for (int nt = 0; nt < 16; nt++) {
            int col = nt * 8 + tg * 2;
            float2 qv = *(const float2*)&qd[col];
            float2 da = *(const float2*)&g_relDen[ra * Dc + col];
            float2 db = *(const float2*)&g_relDen[rb * Dc + col];
            float2 w2 = *(const float2*)&den_W2[col];
            sda += fmaxf(d[nt][0] + da.x + qv.x, 0.0f) * w2.x
                 + fmaxf(d[nt][1] + da.y + qv.y, 0.0f) * w2.y;
            sdb += fmaxf(d[nt][2] + db.x + qv.x, 0.0f) * w2.x
                 + fmaxf(d[nt][3] + db.y + qv.y, 0.0f) * w2.y;
        }
        sda += __shfl_xor_sync(0xffffffffu, sda, 1); sda += __shfl_xor_sync(0xffffffffu, sda, 2);
        sdb += __shfl_xor_sync(0xffffffffu, sdb, 1); sdb += __shfl_xor_sync(0xffffffffu, sdb, 2);
        if (tg == 0) {
            float bv = den_b2[0];
            int es[2] = {ea, eb};
            float ss[2] = {sda, sdb};
            int rr2[2] = {ra, rb};
            #pragma unroll
            for (int q = 0; q < 2; q++) {
                int e = es[q], rel = rr2[q];
                float den = sgm(ss[q] + bv);
                den *= ldmask(emk, e) ? 1.0f : 0.0f;
                float beta = sgm(g_relBeta[rel] + g_rqBeta[b]);
                float gate = ldmask(ecm, e) ? sgm((scores[e] - beta) * 10.0f) : 0.5f;
                g_gd[e] = gate * den;
            }
        }
    }
}

// ---------------- K3: weighted message scatter ----------------
__global__ void scatter_kernel(const int* __restrict__ edge_index) {
    int gt = blockIdx.x * blockDim.x + threadIdx.x;
    int glob = gt >> 5;
    int l = threadIdx.x & 31;
    if (glob >= BEc) return;
    int b = glob >> 15, ebi = glob & (Ec - 1);
    float wv = 0.0f;
    int tgt = 0;
    if (l == 0) {
        tgt = edge_index[(size_t)(b * 2 + 1) * Ec + ebi];
        float gd = g_gd[glob];
        if (gd != 0.0f) {
            float ex = g_att[glob];
            if (ex != 0.0f) {
                float sden = g_sm[b * Nc + tgt];
                wv = gd * ex / (sden + 1e-8f);
            }
        }
    }
    wv  = __shfl_sync(0xffffffffu, wv, 0);
    tgt = __shfl_sync(0xffffffffu, tgt, 0);
    if (wv != 0.0f) {
        float4 rm = *(const float4*)&g_raw[((size_t)glob) * Dc + 4 * l];
        float4 v = make_float4(wv * rm.x, wv * rm.y, wv * rm.z, wv * rm.w);
        red_v4(&g_aggr[((size_t)(b * Nc + tgt)) * Dc + 4 * l], v);
    }
}

// ---------------- K4: update GEMM + LN (+ reset + fused hW2 for next layer) ----------------
__global__ void __launch_bounds__(256, 1)
upd_kernel(int k, int doNext, const float* __restrict__ upd_W, const float* __restrict__ upd_b,
           const float* __restrict__ ln_g, const float* __restrict__ ln_b,
           const float* __restrict__ msg_W, float* __restrict__ out) {
    extern __shared__ float smemf[];
    float* Ws = smemf;
    float* Ag = smemf + 128 * INSTRIDE;
    __shared__ float mus[64], rst[64];
    int tid = threadIdx.x;
    int w = tid >> 5, l = tid & 31;
    int n0 = blockIdx.x * 64;
    #pragma unroll
    for (int rr = 0; rr < 16; rr++) {
        int kk = w * 16 + rr;
        *(float4*)&Ws[kk * INSTRIDE + 4 * l] = *(const float4*)&upd_W[((size_t)k * Dc + kk) * Dc + 4 * l];
    }
    #pragma unroll
    for (int rr = 0; rr < 8; rr++) {
        int nl = w * 8 + rr;
        *(float4*)&Ag[nl * INSTRIDE + 4 * l] = *(const float4*)&g_aggr[((size_t)(n0 + nl)) * Dc + 4 * l];
    }
    __syncthreads();
    int ty = tid >> 4, tx = tid & 15;
    unsigned long long acc[4][4] = {};
    #pragma unroll 2
    for (int kk4 = 0; kk4 < Dc; kk4 += 4) {
        float avv[4][4];
        #pragma unroll
        for (int r = 0; r < 4; r++)
            *(float4*)avv[r] = *(const float4*)&Ag[(ty * 4 + r) * INSTRIDE + kk4];
        #pragma unroll
        for (int u = 0; u < 4; u++) {
            const ulonglong2* wp = (const ulonglong2*)&Ws[(kk4 + u) * INSTRIDE + tx * 8];
            ulonglong2 wa = wp[0], wb = wp[1];
            #pragma unroll
            for (int r = 0; r < 4; r++) {
                unsigned long long a2 = packdup(avv[r][u]);
                FMA2(acc[r][0], a2, wa.x); FMA2(acc[r][1], a2, wa.y);
                FMA2(acc[r][2], a2, wb.x); FMA2(acc[r][3], a2, wb.y);
            }
        }
    }
    __syncthreads();

    float vbuf[4][8];
    float s1[4] = {0}, s2[4] = {0};
    #pragma unroll
    for (int r = 0; r < 4; r++) {
        int n = n0 + ty * 4 + r;
        float vout[8];
        #pragma unroll
        for (int q = 0; q < 4; q++) { float2 u = unpk(acc[r][q]); vout[2*q] = u.x; vout[2*q+1] = u.y; }
        #pragma unroll
        for (int c = 0; c < 8; c++) {
            int j = tx * 8 + c;
            float v = g_h[((size_t)n) * Dc + j] + vout[c] + upd_b[k * Dc + j];
            vbuf[r][c] = v;
            s1[r] += v;
            s2[r] += v * v;
        }
    }
    float* red1 = Ag;
    float* red2 = Ag + 64 * 17;
    #pragma unroll
    for (int r = 0; r < 4; r++) {
        red1[(ty * 4 + r) * 17 + tx] = s1[r];
        red2[(ty * 4 + r) * 17 + tx] = s2[r];
    }
    __syncthreads();
    if (tid < 64) {
        float a = 0, bb = 0;
        #pragma unroll
        for (int t = 0; t < 16; t++) { a += red1[tid * 17 + t]; bb += red2[tid * 17 + t]; }
        float mu = a * (1.0f / Dc);
        float var = bb * (1.0f / Dc) - mu * mu;
        mus[tid] = mu;
        rst[tid] = rsqrtf(var + 1e-5f);
    }
    __syncthreads();
    #pragma unroll
    for (int r = 0; r < 4; r++) {
        int nl = ty * 4 + r;
        int n = n0 + nl;
        float mu = mus[nl], rs = rst[nl];
        float y[8];
        #pragma unroll
        for (int c = 0; c < 8; c++) {
            int j = tx * 8 + c;
            y[c] = (vbuf[r][c] - mu) * rs * ln_g[j] + ln_b[j];
        }
        *(float4*)&g_h[((size_t)n) * Dc + tx * 8]     = make_float4(y[0], y[1], y[2], y[3]);
        *(float4*)&g_h[((size_t)n) * Dc + tx * 8 + 4] = make_float4(y[4], y[5], y[6], y[7]);
        *(float4*)&Ag[nl * INSTRIDE + tx * 8]     = make_float4(y[0], y[1], y[2], y[3]);
        *(float4*)&Ag[nl * INSTRIDE + tx * 8 + 4] = make_float4(y[4], y[5], y[6], y[7]);
        if ((n & (Nc - 1)) == 0) {
            int b = n >> 11;
            #pragma unroll
            for (int c = 0; c < 8; c++) out[((size_t)b * Lc + k) * Dc + tx * 8 + c] = y[c];
        }
    }

    if (doNext) {
        float4 z = make_float4(0, 0, 0, 0);
        #pragma unroll
        for (int rr = 0; rr < 8; rr++) {
            int nl = w * 8 + rr;
            *(float4*)&g_aggr[((size_t)(n0 + nl)) * Dc + 4 * l] = z;
        }
        if (tid < 64) g_sm[n0 + tid] = 0.0f;
        __syncthreads();
        #pragma unroll
        for (int rr = 0; rr < 16; rr++) {
            int kk = w * 16 + rr;
            *(float4*)&Ws[kk * INSTRIDE + 4 * l] =
                *(const float4*)&msg_W[((size_t)(k + 1) * 640 + 128 + kk) * Dc + 4 * l];
        }
        __syncthreads();
        unsigned long long acc2[4][4] = {};
        #pragma unroll 2
        for (int kk4 = 0; kk4 < Dc; kk4 += 4) {
            float avv[4][4];
            #pragma unroll
            for (int r = 0; r < 4; r++)
                *(float4*)avv[r] = *(const float4*)&Ag[(ty * 4 + r) * INSTRIDE + kk4];
            #pragma unroll
            for (int u = 0; u < 4; u++) {
                const ulonglong2* wp = (const ulonglong2*)&Ws[(kk4 + u) * INSTRIDE + tx * 8];
                ulonglong2 wa = wp[0], wb = wp[1];
                #pragma unroll
                for (int r = 0; r < 4; r++) {
                    unsigned long long a2 = packdup(avv[r][u]);
                    FMA2(acc2[r][0], a2, wa.x); FMA2(acc2[r][1], a2, wa.y);
                    FMA2(acc2[r][2], a2, wb.x); FMA2(acc2[r][3], a2, wb.y);
                }
            }
        }
        #pragma unroll
        for (int r = 0; r < 4; r++) {
            int n = n0 + ty * 4 + r;
            float vout[8];
            #pragma unroll
            for (int q = 0; q < 4; q++) { float2 u = unpk(acc2[r][q]); vout[2*q] = u.x; vout[2*q+1] = u.y; }
            *(float4*)&g_hW2[((size_t)n) * Dc + tx * 8]     = make_float4(vout[0], vout[1], vout[2], vout[3]);
            *(float4*)&g_hW2[((size_t)n) * Dc + tx * 8 + 4] = make_float4(vout[4], vout[5], vout[6], vout[7]);
        }
    }
}

// ---------------- launch ----------------
extern "C" void kernel_launch(void* const* d_in, const int* in_sizes, int n_in,
                              void* d_out, int out_size) {
    const int*   edge_index = (const int*)d_in[0];
    const int*   rels       = (const int*)d_in[1];
    const float* scores     = (const float*)d_in[2];
    const void*  ecm        = d_in[3];
    const void*  emk        = d_in[4];
    // d_in[5] = mask (unused)
    const float* rq         = (const float*)d_in[6];
    const float* conf       = (const float*)d_in[7];
    const float* rel_table  = (const float*)d_in[8];
    const float* beta_W     = (const float*)d_in[9];
    const float* beta_b     = (const float*)d_in[10];
    const float* msg_W      = (const float*)d_in[11];
    const float* msg_b      = (const float*)d_in[12];
    const float* upd_W      = (const float*)d_in[13];
    const float* upd_b      = (const float*)d_in[14];
    const float* ln_g       = (const float*)d_in[15];
    const float* ln_b       = (const float*)d_in[16];
    const float* att_W      = (const float*)d_in[17];
    const float* att_b      = (const float*)d_in[18];
    const float* den_W1     = (const float*)d_in[19];
    const float* den_b1     = (const float*)d_in[20];
    const float* den_W2     = (const float*)d_in[21];
    const float* den_b2     = (const float*)d_in[22];
    float* out = (float*)d_out;

    cudaFuncSetAttribute(msg_mma_kernel, cudaFuncAttributeMaxDynamicSharedMemorySize, SMEM_MMA);
    cudaFuncSetAttribute(upd_kernel,     cudaFuncAttributeMaxDynamicSharedMemorySize, SMEM_UPD);

    init_all_kernel<<<(Bc * Nc * Dc) / 256, 256>>>((const unsigned*)emk);
    prep_combo_kernel<<<232, 256>>>(msg_W, den_W1, rq, den_b1, beta_W, beta_b, att_W, att_b);
    rel_tables_kernel<<<250, 512>>>(rel_table, den_W1, msg_W, msg_b, beta_W, att_W);

    for (int k = 0; k < Lc; k++) {
        msg_mma_kernel<<<BEc / TILE, 512, SMEM_MMA>>>(k, edge_index, rels, emk, rel_table,
                                                      conf, att_W, scores, ecm, den_W2, den_b2);
        scatter_kernel<<<(BEc * 32) / 256, 256>>>(edge_index);
        upd_kernel<<<(Bc * Nc) / 64, 256, SMEM_UPD>>>(k, (k < Lc - 1) ? 1 : 0,
                                                      upd_W, upd_b, ln_g, ln_b, msg_W, out);
    }
}

// round 17
// speedup vs baseline: 1.3562x; 1.2873x over previous
#include <cuda_runtime.h>
#include <cuda_bf16.h>
#include <cstdint>
#include <cstddef>

#define Bc 4
#define Nc 2048
#define Ec 32768
#define Dc 128
#define Lc 3
#define NRELc 1000
#define BEc (Bc*Ec)          // 131072 edges

// ---------------- static device scratch ----------------
__device__ float    g_h[Bc*Nc*Dc];
__device__ float    g_aggr[Bc*Nc*Dc];         // UNNORMALIZED weighted sums
__device__ float    g_sm[Bc*Nc];              // softmax denominators
__device__ float    g_gd[BEc];
__device__ float    g_relMsg[Lc*NRELc*Dc];    // h_r@W4 + msg_b
__device__ float    g_relDen[NRELc*Dc];
__device__ float    g_relBeta[NRELc];
__device__ float    g_relAtt[Lc*NRELc];
__device__ float    g_rqDen[Bc*Dc];
__device__ float    g_rqBeta[Bc];
__device__ float    g_rqAtt[Lc*Bc];
__device__ float    g_z0add[Lc*Dc];           // colsum(W3[k]) + (k==0)*colsum(W2[0])
__device__ float    g_hW2[Bc*Nc*Dc];          // h @ W2[k]   (layers 1,2)
__device__ uint2    g_Wfrag[7*8192];          // fragment-packed tf32 weights
__device__ int      g_mflag = 0;              // zero-init; only OR'd with 1 (deterministic)

// ---------------- helpers ----------------
__device__ __forceinline__ float sgm(float x) { return 1.0f / (1.0f + __expf(-x)); }
__device__ __forceinline__ int ldmask(const void* p, int i) {
    return g_mflag ? (int)((const unsigned char*)p)[i] : ((const int*)p)[i];
}
__device__ __forceinline__ unsigned long long packdup(float a) {
    unsigned long long r; unsigned u = __float_as_uint(a);
    asm("mov.b64 %0, {%1, %1};" : "=l"(r) : "r"(u));
    return r;
}
__device__ __forceinline__ float2 unpk(unsigned long long v) {
    float2 f;
    asm("mov.b64 {%0, %1}, %2;" : "=f"(f.x), "=f"(f.y) : "l"(v));
    return f;
}
#define FMA2(acc, a, b) asm("fma.rn.f32x2 %0, %1, %2, %0;" : "+l"(acc) : "l"(a), "l"(b))
__device__ __forceinline__ void red_v2(float* p, float a, float b) {
    asm volatile("red.global.add.v2.f32 [%0], {%1,%2};"
                 :: "l"(p), "f"(a), "f"(b) : "memory");
}
__device__ __forceinline__ uint32_t f2tf(float x) {
    uint32_t r; asm("cvt.rna.tf32.f32 %0, %1;" : "=r"(r) : "f"(x)); return r;
}
__device__ __forceinline__ void mma_tf32(float& d0, float& d1, float& d2, float& d3,
                                         uint32_t a0, uint32_t a1, uint32_t a2, uint32_t a3,
                                         uint32_t b0, uint32_t b1) {
    asm volatile(
        "mma.sync.aligned.m16n8k8.row.col.f32.tf32.tf32.f32 "
        "{%0,%1,%2,%3}, {%4,%5,%6,%7}, {%8,%9}, {%0,%1,%2,%3};"
        : "+f"(d0), "+f"(d1), "+f"(d2), "+f"(d3)
        : "r"(a0), "r"(a1), "r"(a2), "r"(a3), "r"(b0), "r"(b1));
}

#define INSTRIDE 132
#define SMEM_UPD ((128*INSTRIDE + 64*INSTRIDE)*4)
#define ASTRF 132                                  // fp32/tf32 A row stride (floats)
#define TILE 256                                   // edges per MMA block
#define SMEM_MMA (TILE*ASTRF*4 + 8192*8)           // 135168 + 65536 = 200704 B

// ---------------- upfront init (layer 0 state + mask detect) ----------------
__global__ void init_all_kernel(const unsigned* __restrict__ emk32) {
    int idx = blockIdx.x * 256 + threadIdx.x;
    g_aggr[idx] = 0.0f;
    int n = (idx >> 7) & (Nc - 1);
    g_h[idx] = (n == 0) ? 1.0f : 0.0f;
    if (idx < Bc * Nc) g_sm[idx] = 0.0f;
    if (idx < BEc / 4) {                      // 32768 words = BEc bytes
        if (emk32[idx] & 0xFFFFFF00u) atomicOr(&g_mflag, 1);
    }
}

// ---------------- prep combo: tf32 weight fragments (blk<224) + batch vectors ----------------
// wfrag tiles: 0..2 = W1[k], 3..5 = W5[k], 6 = A3 (den_W1 rows 256..383)
__global__ void prep_combo_kernel(const float* __restrict__ msg_W,
                                  const float* __restrict__ den_W1,
                                  const float* __restrict__ rq,
                                  const float* __restrict__ den_b1,
                                  const float* __restrict__ beta_W,
                                  const float* __restrict__ beta_b,
                                  const float* __restrict__ att_W,
                                  const float* __restrict__ att_b) {
    if (blockIdx.x < 224) {
        int idx = blockIdx.x * 256 + threadIdx.x;   // 7*8192
        int tile = idx >> 13;
        int r = idx & 8191;
        int ks = r >> 9;                 // 0..15
        int nt = (r >> 5) & 15;
        int lane = r & 31;
        int g = lane >> 2, tg = lane & 3;
        int n = nt * 8 + g;
        int k0 = ks * 8 + tg;
        const float* base;
        if (tile < 3)      base = msg_W + ((size_t)tile * 640) * Dc;
        else if (tile < 6) base = msg_W + ((size_t)(tile - 3) * 640 + 512) * Dc;
        else               base = den_W1 + (size_t)256 * Dc;
        uint32_t b0 = f2tf(base[(size_t)k0 * Dc + n]);
        uint32_t b1 = f2tf(base[(size_t)(k0 + 4) * Dc + n]);
        g_Wfrag[idx] = make_uint2(b0, b1);
        return;
    }
    int blk = blockIdx.x - 224;                 // 0..7
    int j = threadIdx.x;
    if (j >= 128) return;
    if (blk < 4) {
        int b = blk;
        float acc = 0;
        for (int i = 0; i < Dc; i++) acc += rq[b * Dc + i] * den_W1[(Dc + i) * Dc + j];
        g_rqDen[b * Dc + j] = acc + den_b1[j];
    } else if (blk < 7) {
        int k = blk - 4;
        float s = 0;
        for (int i = 0; i < Dc; i++) s += msg_W[(k * 640 + 256 + i) * Dc + j];
        if (k == 0)
            for (int i = 0; i < Dc; i++) s += msg_W[(0 * 640 + 128 + i) * Dc + j];
        g_z0add[k * Dc + j] = s;
    } else {
        if (j < Bc) {
            float s = 0;
            for (int i = 0; i < Dc; i++) s += rq[j * Dc + i] * beta_W[i];
            g_rqBeta[j] = s + beta_b[0];
        }
        if (j < Lc * Bc) {
            int k = j / Bc, b = j % Bc;
            float s = 0;
            for (int i = 0; i < Dc; i++) s += rq[b * Dc + i] * att_W[k * 384 + 256 + i];
            g_rqAtt[k * Bc + b] = s + att_b[k];
        }
    }
}

// ---------------- P0: per-relation tables (4-way K split, 512 threads) ----------------
__global__ void __launch_bounds__(512, 1)
rel_tables_kernel(const float* __restrict__ rel_table,
                  const float* __restrict__ den_W1,
                  const float* __restrict__ msg_W,
                  const float* __restrict__ msg_b,
                  const float* __restrict__ beta_W,
                  const float* __restrict__ att_W) {
    __shared__ float hr[4][Dc];
    __shared__ float part[4][4][4][Dc];   // [kquart][rel][mat][col] = 32 KB
    int tid = threadIdx.x;
    int col = tid & 127, kq = tid >> 7;   // kq in 0..3
    int r0 = blockIdx.x * 4;              // 250 blocks * 4 = 1000
    hr[tid >> 7][tid & 127] = rel_table[(size_t)(r0 + (tid >> 7)) * Dc + (tid & 127)];
    __syncthreads();
    float aD[4] = {0}, a0[4] = {0}, a1[4] = {0}, a2[4] = {0};
    int i0 = kq * 32;
    #pragma unroll 4
    for (int ii = 0; ii < 32; ii++) {
        int i = i0 + ii;
        float wD = den_W1[i * Dc + col];
        float w0 = msg_W[(0 * 640 + 384 + i) * Dc + col];
        float w1 = msg_W[(1 * 640 + 384 + i) * Dc + col];
        float w2 = msg_W[(2 * 640 + 384 + i) * Dc + col];
        #pragma unroll
        for (int u = 0; u < 4; u++) {
            float h = hr[u][i];
            aD[u] += h * wD; a0[u] += h * w0; a1[u] += h * w1; a2[u] += h * w2;
        }
    }
    #pragma unroll
    for (int u = 0; u < 4; u++) {
        part[kq][u][0][col] = aD[u];
        part[kq][u][1][col] = a0[u];
        part[kq][u][2][col] = a1[u];
        part[kq][u][3][col] = a2[u];
    }
    __syncthreads();
    {
        int u = kq;
        int r = r0 + u;
        float sD = part[0][u][0][col] + part[1][u][0][col] + part[2][u][0][col] + part[3][u][0][col];
        float s0 = part[0][u][1][col] + part[1][u][1][col] + part[2][u][1][col] + part[3][u][1][col];
        float s1 = part[0][u][2][col] + part[1][u][2][col] + part[2][u][2][col] + part[3][u][2][col];
        float s2 = part[0][u][3][col] + part[1][u][3][col] + part[2][u][3][col] + part[3][u][3][col];
        g_relDen[r * Dc + col] = sD;
        g_relMsg[(0 * NRELc + r) * Dc + col] = s0 + msg_b[col];
        g_relMsg[(1 * NRELc + r) * Dc + col] = s1 + msg_b[Dc + col];
        g_relMsg[(2 * NRELc + r) * Dc + col] = s2 + msg_b[2 * Dc + col];
    }
    if (tid < 4) {
        float s = 0;
        for (int i = 0; i < Dc; i++) s += hr[tid][i] * beta_W[i];
        g_relBeta[r0 + tid] = s;
    } else if (tid < 16) {
        int t = tid - 4; int u = t / 3, k = t % 3;
        float s = 0;
        for (int i = 0; i < Dc; i++) s += hr[u][i] * att_W[k * 384 + 128 + i];
        g_relAtt[k * NRELc + (r0 + u)] = s;
    }
}

// ---------------- msg MMA (tf32) + fused aggregation ----------------
// k==0: [A3 pass -> gd] then [W1 pass] then [W5 pass] then epilogue-with-reds.
// k>0 : gd loaded from g_gd.
__global__ void __launch_bounds__(512, 1)
msg_mma_kernel(int k, const int* __restrict__ edge_index, const int* __restrict__ rels_g,
               const void* __restrict__ emk, const float* __restrict__ rel_table,
               const float* __restrict__ conf, const float* __restrict__ att_W,
               const float* __restrict__ scores, const void* __restrict__ ecm,
               const float* __restrict__ den_W2, const float* __restrict__ den_b2) {
    extern __shared__ char sm[];
    float* As = (float*)sm;                         // TILE x 132 tf32-rounded floats
    uint2* Bsm = (uint2*)(sm + TILE * ASTRF * 4);   // 8192 uint2
    __shared__ int s_src[TILE];
    __shared__ int s_rel[TILE];
    __shared__ float s_aw[128];
    int tid = threadIdx.x, w = tid >> 5, lane = tid & 31;
    int g = lane >> 2, tg = lane & 3;
    int e0 = blockIdx.x * TILE, b = e0 >> 15;
    int ebi0 = e0 & (Ec - 1);
    int R = w * 16;
    int r0 = R + g, r1 = R + g + 8;
    int ea = e0 + r0, eb = e0 + r1;

    if (lane < 16) {
        s_src[R + lane] = edge_index[(size_t)b * 2 * Ec + ebi0 + R + lane];
        s_rel[R + lane] = rels_g[e0 + R + lane];
    }
    if (tid < 128) s_aw[tid] = att_W[(size_t)k * 384 + tid];
    __syncwarp();

    float d[16][4];
    float gda, gdb;

    if (k == 0) {
        // ---- A3 pass: B = A3, A = tf32(conf) -> den/gate ----
        for (int i = tid; i < 8192; i += 512) Bsm[i] = g_Wfrag[6 * 8192 + i];
        {
            int c4 = lane * 4;
            #pragma unroll
            for (int rr = 0; rr < 16; rr++) {
                int row = R + rr;
                float4 v = *(const float4*)&conf[((size_t)(e0 + row)) * Dc + c4];
                float4 t = make_float4(__uint_as_float(f2tf(v.x)), __uint_as_float(f2tf(v.y)),
                                       __uint_as_float(f2tf(v.z)), __uint_as_float(f2tf(v.w)));
                *(float4*)&As[row * ASTRF + c4] = t;
            }
        }
        __syncthreads();
        #pragma unroll
        for (int t = 0; t < 16; t++) { d[t][0] = d[t][1] = d[t][2] = d[t][3] = 0.0f; }
        #pragma unroll
        for (int ks = 0; ks < 16; ks++) {
            int ko = ks * 8 + tg;
            uint32_t a0 = __float_as_uint(As[r0 * ASTRF + ko]);
            uint32_t a1 = __float_as_uint(As[r1 * ASTRF + ko]);
            uint32_t a2 = __float_as_uint(As[r0 * ASTRF + ko + 4]);
            uint32_t a3 = __float_as_uint(As[r1 * ASTRF + ko + 4]);
            #pragma unroll
            for (int nt = 0; nt < 16; nt++) {
                uint2 bf = Bsm[(ks * 16 + nt) * 32 + lane];
                mma_tf32(d[nt][0], d[nt][1], d[nt][2], d[nt][3], a0, a1, a2, a3, bf.x, bf.y);
            }
        }
        {
            int ra = s_rel[r0], rb = s_rel[r1];
            const float* qd = &g_rqDen[b * Dc];
            float sda = 0, sdb = 0;
            #pragma unroll
            for (int nt = 0; nt < 16; nt++) {
                int col = nt * 8 + tg * 2;
                float2 qv = *(const float2*)&qd[col];
                float2 da = *(const float2*)&g_relDen[ra * Dc + col];
                float2 db = *(const float2*)&g_relDen[rb * Dc + col];
                float2 w2 = *(const float2*)&den_W2[col];
                sda += fmaxf(d[nt][0] + da.x + qv.x, 0.0f) * w2.x
                     + fmaxf(d[nt][1] + da.y + qv.y, 0.0f) * w2.y;
                sdb += fmaxf(d[nt][2] + db.x + qv.x, 0.0f) * w2.x
                     + fmaxf(d[nt][3] + db.y + qv.y, 0.0f) * w2.y;
            }
            sda += __shfl_xor_sync(0xffffffffu, sda, 1); sda += __shfl_xor_sync(0xffffffffu, sda, 2);
            sdb += __shfl_xor_sync(0xffffffffu, sdb, 1); sdb += __shfl_xor_sync(0xffffffffu, sdb, 2);
            float bv = den_b2[0];
            float dena = sgm(sda + bv) * (ldmask(emk, ea) ? 1.0f : 0.0f);
            float denb = sgm(sdb + bv) * (ldmask(emk, eb) ? 1.0f : 0.0f);
            float betaa = sgm(g_relBeta[ra] + g_rqBeta[b]);
            float betab = sgm(g_relBeta[rb] + g_rqBeta[b]);
            float gatea = ldmask(ecm, ea) ? sgm((scores[ea] - betaa) * 10.0f) : 0.5f;
            float gateb = ldmask(ecm, eb) ? sgm((scores[eb] - betab) * 10.0f) : 0.5f;
            gda = gatea * dena;
            gdb = gateb * denb;
            if (tg == 0) { g_gd[ea] = gda; g_gd[eb] = gdb; }
        }
        __syncthreads();       // all warps done with A3 B before overwrite
    } else {
        gda = g_gd[ea];
        gdb = g_gd[eb];
    }

    // ---- phase 1: B = W1[k], A = tf32(h_src * h_r) ----
    for (int i = tid; i < 8192; i += 512) Bsm[i] = g_Wfrag[k * 8192 + i];
    {
        int c4 = lane * 4;
        #pragma unroll
        for (int rr = 0; rr < 16; rr++) {
            int row = R + rr;
            float4 hv = *(const float4*)&g_h[((size_t)(b * Nc + s_src[row])) * Dc + c4];
            float4 rv = *(const float4*)&rel_table[(size_t)s_rel[row] * Dc + c4];
            float4 t = make_float4(__uint_as_float(f2tf(hv.x * rv.x)),
                                   __uint_as_float(f2tf(hv.y * rv.y)),
                                   __uint_as_float(f2tf(hv.z * rv.z)),
                                   __uint_as_float(f2tf(hv.w * rv.w)));
            *(float4*)&As[row * ASTRF + c4] = t;
        }
    }
    __syncthreads();
    #pragma unroll
    for (int t = 0; t < 16; t++) { d[t][0] = d[t][1] = d[t][2] = d[t][3] = 0.0f; }
    #pragma unroll
    for (int ks = 0; ks < 16; ks++) {
        int ko = ks * 8 + tg;
        uint32_t a0 = __float_as_uint(As[r0 * ASTRF + ko]);
        uint32_t a1 = __float_as_uint(As[r1 * ASTRF + ko]);
        uint32_t a2 = __float_as_uint(As[r0 * ASTRF + ko + 4]);
        uint32_t a3 = __float_as_uint(As[r1 * ASTRF + ko + 4]);
        #pragma unroll
        for (int nt = 0; nt < 16; nt++) {
            uint2 bf = Bsm[(ks * 16 + nt) * 32 + lane];
            mma_tf32(d[nt][0], d[nt][1], d[nt][2], d[nt][3], a0, a1, a2, a3, bf.x, bf.y);
        }
    }
    __syncthreads();

    // ---- phase 2: B = W5[k], A = tf32(conf), accumulate ----
    for (int i = tid; i < 8192; i += 512) Bsm[i] = g_Wfrag[(3 + k) * 8192 + i];
    {
        int c4 = lane * 4;
        #pragma unroll
        for (int rr = 0; rr < 16; rr++) {
            int row = R + rr;
            float4 v = *(const float4*)&conf[((size_t)(e0 + row)) * Dc + c4];
            float4 t = make_float4(__uint_as_float(f2tf(v.x)), __uint_as_float(f2tf(v.y)),
                                   __uint_as_float(f2tf(v.z)), __uint_as_float(f2tf(v.w)));
            *(float4*)&As[row * ASTRF + c4] = t;
        }
    }
    __syncthreads();
    #pragma unroll
    for (int ks = 0; ks < 16; ks++) {
        int ko = ks * 8 + tg;
        uint32_t a0 = __float_as_uint(As[r0 * ASTRF + ko]);
        uint32_t a1 = __float_as_uint(As[r1 * ASTRF + ko]);
        uint32_t a2 = __float_as_uint(As[r0 * ASTRF + ko + 4]);
        uint32_t a3 = __float_as_uint(As[r1 * ASTRF + ko + 4]);
        #pragma unroll
        for (int nt = 0; nt < 16; nt++) {
            uint2 bf = Bsm[(ks * 16 + nt) * 32 + lane];
            mma_tf32(d[nt][0], d[nt][1], d[nt][2], d[nt][3], a0, a1, a2, a3, bf.x, bf.y);
        }
    }

    // ---- epilogue: tables + relu (in place in d), att dot, exp, fused reds ----
    int ra = s_rel[r0], rb = s_rel[r1];
    int sa = s_src[r0], sbn = s_src[r1];
    bool za = (sa == 0), zb = (sbn == 0);
    const float* rma = &g_relMsg[((size_t)k * NRELc + ra) * Dc];
    const float* rmb = &g_relMsg[((size_t)k * NRELc + rb) * Dc];
    const float* hwa = &g_hW2[((size_t)(b * Nc + sa)) * Dc];
    const float* hwb = &g_hW2[((size_t)(b * Nc + sbn)) * Dc];
    const float* z0t = &g_z0add[k * Dc];
    float pa = 0, pb = 0;
    #pragma unroll
    for (int nt = 0; nt < 16; nt++) {
        int col = nt * 8 + tg * 2;
        float2 ta = *(const float2*)&rma[col];
        float2 tb = *(const float2*)&rmb[col];
        float v0 = d[nt][0] + ta.x;
        float v1 = d[nt][1] + ta.y;
        float v2 = d[nt][2] + tb.x;
        float v3 = d[nt][3] + tb.y;
        if (k > 0) {
            float2 ha = *(const float2*)&hwa[col];
            float2 hb = *(const float2*)&hwb[col];
            v0 += ha.x; v1 += ha.y; v2 += hb.x; v3 += hb.y;
        }
        if (za || zb) {
            float2 zv = *(const float2*)&z0t[col];
            if (za) { v0 += zv.x; v1 += zv.y; }
            if (zb) { v2 += zv.x; v3 += zv.y; }
        }
        v0 = fmaxf(v0, 0.0f); v1 = fmaxf(v1, 0.0f);
        v2 = fmaxf(v2, 0.0f); v3 = fmaxf(v3, 0.0f);
        float aw0 = s_aw[col], aw1 = s_aw[col + 1];
        pa += v0 * aw0 + v1 * aw1;
        pb += v2 * aw0 + v3 * aw1;
        d[nt][0] = v0; d[nt][1] = v1; d[nt][2] = v2; d[nt][3] = v3;
    }
    pa += __shfl_xor_sync(0xffffffffu, pa, 1); pa += __shfl_xor_sync(0xffffffffu, pa, 2);
    pb += __shfl_xor_sync(0xffffffffu, pb, 1); pb += __shfl_xor_sync(0xffffffffu, pb, 2);

    float atta = pa + g_relAtt[k * NRELc + ra] + g_rqAtt[k * Bc + b];
    float attb = pb + g_relAtt[k * NRELc + rb] + g_rqAtt[k * Bc + b];
    atta = atta > 0.0f ? atta : 0.01f * atta;
    attb = attb > 0.0f ? attb : 0.01f * attb;
    float exa = ldmask(emk, ea) ? __expf(atta) : 0.0f;
    float exb = ldmask(emk, eb) ? __expf(attb) : 0.0f;
    int tgta = edge_index[(size_t)(b * 2 + 1) * Ec + (ea & (Ec - 1))];
    int tgtb = edge_index[(size_t)(b * 2 + 1) * Ec + (eb & (Ec - 1))];
    if (tg == 0) {
        if (exa != 0.0f) atomicAdd(&g_sm[b * Nc + tgta], exa);
        if (exb != 0.0f) atomicAdd(&g_sm[b * Nc + tgtb], exb);
    }
    float wva = gda * exa;
    float wvb = gdb * exb;
    if (wva != 0.0f) {
        float* basep = &g_aggr[((size_t)(b * Nc + tgta)) * Dc + tg * 2];
        #pragma unroll
        for (int nt = 0; nt < 16; nt++)
            red_v2(basep + nt * 8, wva * d[nt][0], wva * d[nt][1]);
    }
    if (wvb != 0.0f) {
        float* basep = &g_aggr[((size_t)(b * Nc + tgtb)) * Dc + tg * 2];
        #pragma unroll
        for (int nt = 0; nt < 16; nt++)
            red_v2(basep + nt * 8, wvb * d[nt][2], wvb * d[nt][3]);
    }
}

// ---------------- K4: update GEMM (scaled by 1/sm) + LN (+ reset + fused hW2) ----------------
__global__ void __launch_bounds__(256, 1)
upd_kernel(int k, int doNext, const float* __restrict__ upd_W, const float* __restrict__ upd_b,
           const float* __restrict__ ln_g, const float* __restrict__ ln_b,
           const float* __restrict__ msg_W, float* __restrict__ out) {
    extern __shared__ float smemf[];
    float* Ws = smemf;
    float* Ag = smemf + 128 * INSTRIDE;
    __shared__ float mus[64], rst[64], ssc[64];
    int tid = threadIdx.x;
    int w = tid >> 5, l = tid & 31;
    int n0 = blockIdx.x * 64;
    if (tid < 64) ssc[tid] = 1.0f / (g_sm[n0 + tid] + 1e-8f);
    #pragma unroll
    for (int rr = 0; rr < 16; rr++) {
        int kk = w * 16 + rr;
        *(float4*)&Ws[kk * INSTRIDE + 4 * l] = *(const float4*)&upd_W[((size_t)k * Dc + kk) * Dc + 4 * l];
    }
    #pragma unroll
    for (int rr = 0; rr < 8; rr++) {
        int nl = w * 8 + rr;
        *(float4*)&Ag[nl * INSTRIDE + 4 * l] = *(const float4*)&g_aggr[((size_t)(n0 + nl)) * Dc + 4 * l];
    }
    __syncthreads();
    int ty = tid >> 4, tx = tid & 15;
    unsigned long long acc[4][4] = {};
    #pragma unroll 2
    for (int kk4 = 0; kk4 < Dc; kk4 += 4) {
        float avv[4][4];
        #pragma unroll
        for (int r = 0; r < 4; r++)
            *(float4*)avv[r] = *(const float4*)&Ag[(ty * 4 + r) * INSTRIDE + kk4];
        #pragma unroll
        for (int u = 0; u < 4; u++) {
            const ulonglong2* wp = (const ulonglong2*)&Ws[(kk4 + u) * INSTRIDE + tx * 8];
            ulonglong2 wa = wp[0], wb = wp[1];
            #pragma unroll
            for (int r = 0; r < 4; r++) {
                unsigned long long a2 = packdup(avv[r][u]);
                FMA2(acc[r][0], a2, wa.x); FMA2(acc[r][1], a2, wa.y);
                FMA2(acc[r][2], a2, wb.x); FMA2(acc[r][3], a2, wb.y);
            }
        }
    }
    __syncthreads();

    float vbuf[4][8];
    float s1[4] = {0}, s2[4] = {0};
    #pragma unroll
    for (int r = 0; r < 4; r++) {
        int nl = ty * 4 + r;
        int n = n0 + nl;
        float sc = ssc[nl];
        float vout[8];
        #pragma unroll
        for (int q = 0; q < 4; q++) { float2 u = unpk(acc[r][q]); vout[2*q] = u.x; vout[2*q+1] = u.y; }
        #pragma unroll
        for (int c = 0; c < 8; c++) {
            int j = tx * 8 + c;
            float v = g_h[((size_t)n) * Dc + j] + sc * vout[c] + upd_b[k * Dc + j];
            vbuf[r][c] = v;
            s1[r] += v;
            s2[r] += v * v;
        }
    }
    float* red1 = Ag;
    float* red2 = Ag + 64 * 17;
    #pragma unroll
    for (int r = 0; r < 4; r++) {
        red1[(ty * 4 + r) * 17 + tx] = s1[r];
        red2[(ty * 4 + r) * 17 + tx] = s2[r];
    }
    __syncthreads();
    if (tid < 64) {
        float a = 0, bb = 0;
        #pragma unroll
        for (int t = 0; t < 16; t++) { a += red1[tid * 17 + t]; bb += red2[tid * 17 + t]; }
        float mu = a * (1.0f / Dc);
        float var = bb * (1.0f / Dc) - mu * mu;
        mus[tid] = mu;
        rst[tid] = rsqrtf(var + 1e-5f);
    }
    __syncthreads();
    #pragma unroll
    for (int r = 0; r < 4; r++) {
        int nl = ty * 4 + r;
        int n = n0 + nl;
        float mu = mus[nl], rs = rst[nl];
        float y[8];
        #pragma unroll
        for (int c = 0; c < 8; c++) {
            int j = tx * 8 + c;
            y[c] = (vbuf[r][c] - mu) * rs * ln_g[j] + ln_b[j];
        }
        *(float4*)&g_h[((size_t)n) * Dc + tx * 8]     = make_float4(y[0], y[1], y[2], y[3]);
        *(float4*)&g_h[((size_t)n) * Dc + tx * 8 + 4] = make_float4(y[4], y[5], y[6], y[7]);
        *(float4*)&Ag[nl * INSTRIDE + tx * 8]     = make_float4(y[0], y[1], y[2], y[3]);
        *(float4*)&Ag[nl * INSTRIDE + tx * 8 + 4] = make_float4(y[4], y[5], y[6], y[7]);
        if ((n & (Nc - 1)) == 0) {
            int b = n >> 11;
            #pragma unroll
            for (int c = 0; c < 8; c++) out[((size_t)b * Lc + k) * Dc + tx * 8 + c] = y[c];
        }
    }

    if (doNext) {
        float4 z = make_float4(0, 0, 0, 0);
        #pragma unroll
        for (int rr = 0; rr < 8; rr++) {
            int nl = w * 8 + rr;
            *(float4*)&g_aggr[((size_t)(n0 + nl)) * Dc + 4 * l] = z;
        }
        if (tid < 64) g_sm[n0 + tid] = 0.0f;
        __syncthreads();
        #pragma unroll
        for (int rr = 0; rr < 16; rr++) {
            int kk = w * 16 + rr;
            *(float4*)&Ws[kk * INSTRIDE + 4 * l] =
                *(const float4*)&msg_W[((size_t)(k + 1) * 640 + 128 + kk) * Dc + 4 * l];
        }
        __syncthreads();
        unsigned long long acc2[4][4] = {};
        #pragma unroll 2
        for (int kk4 = 0; kk4 < Dc; kk4 += 4) {
            float avv[4][4];
            #pragma unroll
            for (int r = 0; r < 4; r++)
                *(float4*)avv[r] = *(const float4*)&Ag[(ty * 4 + r) * INSTRIDE + kk4];
            #pragma unroll
            for (int u = 0; u < 4; u++) {
                const ulonglong2* wp = (const ulonglong2*)&Ws[(kk4 + u) * INSTRIDE + tx * 8];
                ulonglong2 wa = wp[0], wb = wp[1];
                #pragma unroll
                for (int r = 0; r < 4; r++) {
                    unsigned long long a2 = packdup(avv[r][u]);
                    FMA2(acc2[r][0], a2, wa.x); FMA2(acc2[r][1], a2, wa.y);
                    FMA2(acc2[r][2], a2, wb.x); FMA2(acc2[r][3], a2, wb.y);
                }
            }
        }
        #pragma unroll
        for (int r = 0; r < 4; r++) {
            int n = n0 + ty * 4 + r;
            float vout[8];
            #pragma unroll
            for (int q = 0; q < 4; q++) { float2 u = unpk(acc2[r][q]); vout[2*q] = u.x; vout[2*q+1] = u.y; }
            *(float4*)&g_hW2[((size_t)n) * Dc + tx * 8]     = make_float4(vout[0], vout[1], vout[2], vout[3]);
            *(float4*)&g_hW2[((size_t)n) * Dc + tx * 8 + 4] = make_float4(vout[4], vout[5], vout[6], vout[7]);
        }
    }
}

// ---------------- launch ----------------
extern "C" void kernel_launch(void* const* d_in, const int* in_sizes, int n_in,
                              void* d_out, int out_size) {
    const int*   edge_index = (const int*)d_in[0];
    const int*   rels       = (const int*)d_in[1];
    const float* scores     = (const float*)d_in[2];
    const void*  ecm        = d_in[3];
    const void*  emk        = d_in[4];
    // d_in[5] = mask (unused)
    const float* rq         = (const float*)d_in[6];
    const float* conf       = (const float*)d_in[7];
    const float* rel_table  = (const float*)d_in[8];
    const float* beta_W     = (const float*)d_in[9];
    const float* beta_b     = (const float*)d_in[10];
    const float* msg_W      = (const float*)d_in[11];
    const float* msg_b      = (const float*)d_in[12];
    const float* upd_W      = (const float*)d_in[13];
    const float* upd_b      = (const float*)d_in[14];
    const float* ln_g       = (const float*)d_in[15];
    const float* ln_b       = (const float*)d_in[16];
    const float* att_W      = (const float*)d_in[17];
    const float* att_b      = (const float*)d_in[18];
    const float* den_W1     = (const float*)d_in[19];
    const float* den_b1     = (const float*)d_in[20];
    const float* den_W2     = (const float*)d_in[21];
    const float* den_b2     = (const float*)d_in[22];
    float* out = (float*)d_out;

    cudaFuncSetAttribute(msg_mma_kernel, cudaFuncAttributeMaxDynamicSharedMemorySize, SMEM_MMA);
    cudaFuncSetAttribute(upd_kernel,     cudaFuncAttributeMaxDynamicSharedMemorySize, SMEM_UPD);

    init_all_kernel<<<(Bc * Nc * Dc) / 256, 256>>>((const unsigned*)emk);
    prep_combo_kernel<<<232, 256>>>(msg_W, den_W1, rq, den_b1, beta_W, beta_b, att_W, att_b);
    rel_tables_kernel<<<250, 512>>>(rel_table, den_W1, msg_W, msg_b, beta_W, att_W);

    for (int k = 0; k < Lc; k++) {
        msg_mma_kernel<<<BEc / TILE, 512, SMEM_MMA>>>(k, edge_index, rels, emk, rel_table,
                                                      conf, att_W, scores, ecm, den_W2, den_b2);
        upd_kernel<<<(Bc * Nc) / 64, 256, SMEM_UPD>>>(k, (k < Lc - 1) ? 1 : 0,
                                                      upd_W, upd_b, ln_g, ln_b, msg_W, out);
    }
}